// round 14
// baseline (speedup 1.0000x reference)
#include <cuda_runtime.h>
#include <math.h>

// ---------------- problem constants (fixed by setup_inputs) ----------------
#define NN 4096       // nodes
#define EE 262144     // edges
#define DD 64         // hidden dim
#define LL 3          // layers
#define HH 4          // attention heads
#define DHH 16        // head dim
#define GG 64         // graphs
#define CC 10         // classes
#define NSPLIT 8      // attention key splits

// ---------------- device global scratch (allowed: no runtime alloc) --------
__device__ float g_X   [NN * DD];
__device__ float g_T128[NN * 128];
__device__ float g_XL  [NN * DD];
__device__ float g_XR  [NN * DD];
__device__ float g_H1R [NN * DD];
__device__ float g_H2R [NN * DD];
__device__ float g_OUT0[NN * DD];
__device__ float g_OUT [NN * DD];
__device__ float g_QKV [3 * HH * NN * DHH];   // head-major: [which][h][n][16]

__device__ int g_cnt   [NN];
__device__ int g_rowptr[NN + 1];
__device__ int g_cursor[NN];
__device__ int g_csrsrc[EE];

// BN partial sums: [block][0..63]=sum, [block][64..127]=sumsq
__device__ float g_part1[512 * 128];   // H1R stats (from k_gat, 512 blocks)
__device__ float g_part2[128 * 128];   // H2R stats (from attn_out gemm, 128 blocks)
__device__ float g_part3[128 * 128];   // OUT stats (from mlp2 gemm, 128 blocks)

// attention split partials: 4 heads x NSPLIT splits
__device__ float g_opart[HH * NSPLIT * NN * DHH];
__device__ float g_mpart[HH * NSPLIT * NN];
__device__ float g_lpart[HH * NSPLIT * NN];

__device__ int g_gbound[GG + 1];

// ---------------- f32x2 packed + fast exp2 helpers (sm_10x) ----------------
__device__ __forceinline__ unsigned long long pk2(float x, float y) {
    unsigned long long r;
    asm("mov.b64 %0, {%1, %2};" : "=l"(r) : "f"(x), "f"(y));
    return r;
}
__device__ __forceinline__ void upk2(unsigned long long v, float& x, float& y) {
    asm("mov.b64 {%0, %1}, %2;" : "=f"(x), "=f"(y) : "l"(v));
}
__device__ __forceinline__ unsigned long long ffma2(unsigned long long a, unsigned long long b,
                                                    unsigned long long c) {
    unsigned long long d;
    asm("fma.rn.f32x2 %0, %1, %2, %3;" : "=l"(d) : "l"(a), "l"(b), "l"(c));
    return d;
}
__device__ __forceinline__ unsigned long long fmul2(unsigned long long a, unsigned long long b) {
    unsigned long long d;
    asm("mul.rn.f32x2 %0, %1, %2;" : "=l"(d) : "l"(a), "l"(b));
    return d;
}
__device__ __forceinline__ unsigned long long fadd2(unsigned long long a, unsigned long long b) {
    unsigned long long d;
    asm("add.rn.f32x2 %0, %1, %2;" : "=l"(d) : "l"(a), "l"(b));
    return d;
}
// single MUFU.EX2 — exp2f without fast-math is a multi-instruction routine
__device__ __forceinline__ float ex2f(float x) {
    float y;
    asm("ex2.approx.f32 %0, %1;" : "=f"(y) : "f"(x));
    return y;
}

__device__ __forceinline__ float gelu_exact(float v) {
    return 0.5f * v * (1.0f + erff(v * 0.70710678118654752440f));
}

// buffer selector (host cannot take addresses of __device__ globals)
__device__ __forceinline__ float* bufsel(int id) {
    switch (id) {
        case 0: return g_X;
        case 1: return g_T128;
        case 2: return g_XL;
        case 3: return g_XR;
        case 4: return g_H1R;
        case 5: return g_H2R;
        case 6: return g_OUT0;
        case 7: return g_OUT;
        case 8: return g_QKV;
    }
    return nullptr;
}
__device__ __forceinline__ float* partsel(int id) {
    return (id == 2) ? g_part2 : g_part3;
}

// ---------------- CSR build ------------------------------------------------
__global__ void k_zero_cnt() {
    int t = blockIdx.x * blockDim.x + threadIdx.x;
    if (t < NN) g_cnt[t] = 0;
}

__global__ void k_hist(const int* __restrict__ ei) {
    int e = blockIdx.x * blockDim.x + threadIdx.x;
    if (e < EE) atomicAdd(&g_cnt[ei[EE + e]], 1);
}

__global__ void k_scan() {
    __shared__ int sh[1024];
    int t = threadIdx.x;
    int c0 = g_cnt[4 * t], c1 = g_cnt[4 * t + 1], c2 = g_cnt[4 * t + 2], c3 = g_cnt[4 * t + 3];
    int tot = c0 + c1 + c2 + c3;
    sh[t] = tot;
    __syncthreads();
    for (int off = 1; off < 1024; off <<= 1) {
        int v = 0;
        if (t >= off) v = sh[t - off];
        __syncthreads();
        sh[t] += v;
        __syncthreads();
    }
    int excl = sh[t] - tot;
    int p0 = excl, p1 = excl + c0, p2 = p1 + c1, p3 = p2 + c2;
    g_rowptr[4 * t] = p0; g_rowptr[4 * t + 1] = p1;
    g_rowptr[4 * t + 2] = p2; g_rowptr[4 * t + 3] = p3;
    g_cursor[4 * t] = p0; g_cursor[4 * t + 1] = p1;
    g_cursor[4 * t + 2] = p2; g_cursor[4 * t + 3] = p3;
    if (t == 1023) g_rowptr[NN] = p3 + c3;
}

__global__ void k_scatter(const int* __restrict__ ei) {
    int e = blockIdx.x * blockDim.x + threadIdx.x;
    if (e < EE) {
        int d = ei[EE + e];
        int pos = atomicAdd(&g_cursor[d], 1);
        g_csrsrc[pos] = ei[e];
    }
}

// ---------------- generic small SGEMM (4096 rows) ---------------------------
// C[row, n0+col] = act( sum_k A[row,k]*B(k,col) + bias[col] (+ res[row,col]) )
// ACT: 0 none, 1 gelu, 2 relu.  TB: B given as [Ntot, K] (use B^T).
// STATS >= 0: emit per-block column sum/sumsq partials (y==1, Ntot==64).
// QKVOUT: store to head-major g_QKV layout.
// MERGEA: A tile = attention split-merge of this block's rows (K==64).
// DUAL: blockIdx.y selects (B,bias,out) vs (B2,bias2,out2); n0=0.
// K4: K % 4 == 0 -> packed f32x2 inner loop with float4 A fragments.
template <int ACT, bool TB, bool RES, int STATS, bool QKVOUT, bool MERGEA, bool DUAL, bool K4>
__global__ void __launch_bounds__(256) k_gemm(const float* __restrict__ Aext, int aSel,
                                              const float* __restrict__ B,
                                              const float* __restrict__ bias,
                                              int resSel, int cSel, int Ntot, int K,
                                              const float* __restrict__ B2,
                                              const float* __restrict__ bias2,
                                              int cSel2) {
    __shared__ __align__(16) float As[32 * 128];
    __shared__ __align__(16) float Bs[128 * 64];
    const float* A = (aSel >= 0) ? bufsel(aSel) : Aext;
    float* Cm;
    if (DUAL) {
        if (blockIdx.y == 1) { B = B2; bias = bias2; Cm = bufsel(cSel2); }
        else                 { Cm = bufsel(cSel); }
    } else {
        Cm = bufsel(cSel);
    }
    const float* res = RES ? bufsel(resSel) : nullptr;

    int rb = blockIdx.x * 32;
    int n0 = DUAL ? 0 : blockIdx.y * 64;
    int tid = threadIdx.x;

    if (MERGEA) {
        // A tile = merged attention output for rows rb..rb+31 (K == 64)
        if (tid < 128) {
            int r = tid >> 2, h = tid & 3, q = rb + r;
            float mv[NSPLIT], mb = -1e30f;
#pragma unroll
            for (int sp = 0; sp < NSPLIT; sp++) {
                mv[sp] = g_mpart[(h * NSPLIT + sp) * NN + q];
                mb = fmaxf(mb, mv[sp]);
            }
            float L = 0.f, o[16] = {};
#pragma unroll
            for (int sp = 0; sp < NSPLIT; sp++) {
                float w = ex2f(mv[sp] - mb);
                int pidx = (h * NSPLIT + sp) * NN + q;
                L += g_lpart[pidx] * w;
                const float4* op4 = (const float4*)(g_opart + pidx * 16);
#pragma unroll
                for (int i = 0; i < 4; i++) {
                    float4 vv = op4[i];
                    o[4 * i + 0] = fmaf(vv.x, w, o[4 * i + 0]);
                    o[4 * i + 1] = fmaf(vv.y, w, o[4 * i + 1]);
                    o[4 * i + 2] = fmaf(vv.z, w, o[4 * i + 2]);
                    o[4 * i + 3] = fmaf(vv.w, w, o[4 * i + 3]);
                }
            }
            float inv = 1.0f / L;
#pragma unroll
            for (int d = 0; d < 16; d++) As[r * 64 + h * 16 + d] = o[d] * inv;
        }
    } else {
        for (int idx = tid; idx < 32 * K; idx += 256) As[idx] = A[rb * K + idx];
    }
    for (int idx = tid; idx < K * 64; idx += 256) {
        if (TB) {
            int n = idx / K;
            int k = idx - n * K;
            Bs[k * 64 + n] = B[(n0 + n) * K + k];
        } else {
            int k = idx >> 6;
            int n = idx & 63;
            Bs[k * 64 + n] = B[k * Ntot + n0 + n];
        }
    }
    __syncthreads();

    int tr = tid >> 4;       // 0..15 (rows tr, tr+16)
    int tc = tid & 15;       // 0..15 (cols tc*4..tc*4+3)
    float acc[2][4];
    if (K4) {
        unsigned long long ap00 = 0ull, ap01 = 0ull, ap10 = 0ull, ap11 = 0ull;
        for (int kb = 0; kb < K; kb += 4) {
            float4 av0 = *(const float4*)&As[tr * K + kb];
            float4 av1 = *(const float4*)&As[(tr + 16) * K + kb];
#pragma unroll
            for (int kk = 0; kk < 4; kk++) {
                float a0 = (kk == 0) ? av0.x : (kk == 1) ? av0.y : (kk == 2) ? av0.z : av0.w;
                float a1 = (kk == 0) ? av1.x : (kk == 1) ? av1.y : (kk == 2) ? av1.z : av1.w;
                ulonglong2 bp = *(const ulonglong2*)&Bs[(kb + kk) * 64 + tc * 4];
                unsigned long long a02 = pk2(a0, a0);
                unsigned long long a12 = pk2(a1, a1);
                ap00 = ffma2(a02, bp.x, ap00);
                ap01 = ffma2(a02, bp.y, ap01);
                ap10 = ffma2(a12, bp.x, ap10);
                ap11 = ffma2(a12, bp.y, ap11);
            }
        }
        upk2(ap00, acc[0][0], acc[0][1]);
        upk2(ap01, acc[0][2], acc[0][3]);
        upk2(ap10, acc[1][0], acc[1][1]);
        upk2(ap11, acc[1][2], acc[1][3]);
    } else {
        acc[0][0] = acc[0][1] = acc[0][2] = acc[0][3] = 0.f;
        acc[1][0] = acc[1][1] = acc[1][2] = acc[1][3] = 0.f;
        for (int k = 0; k < K; k++) {
            float a0 = As[tr * K + k];
            float a1 = As[(tr + 16) * K + k];
            float4 b = *(const float4*)&Bs[k * 64 + tc * 4];
            acc[0][0] = fmaf(a0, b.x, acc[0][0]);
            acc[0][1] = fmaf(a0, b.y, acc[0][1]);
            acc[0][2] = fmaf(a0, b.z, acc[0][2]);
            acc[0][3] = fmaf(a0, b.w, acc[0][3]);
            acc[1][0] = fmaf(a1, b.x, acc[1][0]);
            acc[1][1] = fmaf(a1, b.y, acc[1][1]);
            acc[1][2] = fmaf(a1, b.z, acc[1][2]);
            acc[1][3] = fmaf(a1, b.w, acc[1][3]);
        }
    }
    float sl[4] = {}, ql[4] = {};
#pragma unroll
    for (int r = 0; r < 2; r++) {
        int row = rb + tr + r * 16;
#pragma unroll
        for (int i = 0; i < 4; i++) {
            int col = n0 + tc * 4 + i;
            float v = acc[r][i] + bias[col];
            if (RES) v += res[row * Ntot + col];
            if (ACT == 1) v = gelu_exact(v);
            if (ACT == 2) v = fmaxf(v, 0.0f);
            if (QKVOUT) {
                int which = col >> 6, hh = (col >> 4) & 3, d = col & 15;
                g_QKV[which * (HH * NN * DHH) + (hh * NN + row) * DHH + d] = v;
            } else {
                Cm[row * Ntot + col] = v;
            }
            if (STATS >= 0) { sl[i] += v; ql[i] = fmaf(v, v, ql[i]); }
        }
    }
    if (STATS >= 0) {
        __syncthreads();   // done with As main-loop reads
#pragma unroll
        for (int i = 0; i < 4; i++) {
            As[tr * 128 + tc * 4 + i]      = sl[i];
            As[tr * 128 + 64 + tc * 4 + i] = ql[i];
        }
        __syncthreads();
        if (tid < 128) {
            float S = 0.f;
#pragma unroll
            for (int r = 0; r < 16; r++) S += As[r * 128 + tid];
            partsel(STATS)[blockIdx.x * 128 + tid] = S;
        }
    }
}

// ---------------- GATv2: fused one-pass, 4 edge-groups x 8 lanes -----------
__global__ void __launch_bounds__(256) k_gat(const float* __restrict__ att,
                                             const float* __restrict__ gbias) {
    const float L2E = 1.4426950408889634f;
    int warp = threadIdx.x >> 5, lane = threadIdx.x & 31;
    int grp = lane >> 3;
    unsigned gm = 0xFFu << (grp * 8);   // group-local shuffle mask
    int fb = (lane & 7) * 8;            // feature block [fb, fb+8)
    int v = blockIdx.x * 8 + warp;

    float4 xra = *(const float4*)&g_XR[v * 64 + fb];
    float4 xrb = *(const float4*)&g_XR[v * 64 + fb + 4];
    float4 ata = *(const float4*)&att[fb];
    float4 atb = *(const float4*)&att[fb + 4];
    ata.x *= L2E; ata.y *= L2E; ata.z *= L2E; ata.w *= L2E;
    atb.x *= L2E; atb.y *= L2E; atb.z *= L2E; atb.w *= L2E;

#define GAT_SCORE(E, XA, XB)                                                  \
    {                                                                         \
        float z, p = 0.f;                                                     \
        z = XA.x + xra.x; z = fmaxf(z, 0.2f * z); p = fmaf(z, ata.x, p);      \
        z = XA.y + xra.y; z = fmaxf(z, 0.2f * z); p = fmaf(z, ata.y, p);      \
        z = XA.z + xra.z; z = fmaxf(z, 0.2f * z); p = fmaf(z, ata.z, p);      \
        z = XA.w + xra.w; z = fmaxf(z, 0.2f * z); p = fmaf(z, ata.w, p);      \
        z = XB.x + xrb.x; z = fmaxf(z, 0.2f * z); p = fmaf(z, atb.x, p);      \
        z = XB.y + xrb.y; z = fmaxf(z, 0.2f * z); p = fmaf(z, atb.y, p);      \
        z = XB.z + xrb.z; z = fmaxf(z, 0.2f * z); p = fmaf(z, atb.z, p);      \
        z = XB.w + xrb.w; z = fmaxf(z, 0.2f * z); p = fmaf(z, atb.w, p);      \
        p += __shfl_xor_sync(gm, p, 1);                                       \
        p += __shfl_xor_sync(gm, p, 2);                                       \
        p += __shfl_xor_sync(gm, p, 4);                                       \
        E = p;                                                                \
    }

    // self-loop seeds group 0; other groups start empty (m=-inf, l=0, acc=0)
    float4 xa = *(const float4*)&g_XL[v * 64 + fb];
    float4 xb = *(const float4*)&g_XL[v * 64 + fb + 4];
    float e;
    GAT_SCORE(e, xa, xb);
    bool g0 = (grp == 0);
    float m = g0 ? e : -1e30f;
    float l = g0 ? 1.f : 0.f;
    float4 aca, acb;
    aca.x = g0 ? xa.x : 0.f; aca.y = g0 ? xa.y : 0.f;
    aca.z = g0 ? xa.z : 0.f; aca.w = g0 ? xa.w : 0.f;
    acb.x = g0 ? xb.x : 0.f; acb.y = g0 ? xb.y : 0.f;
    acb.z = g0 ? xb.z : 0.f; acb.w = g0 ? xb.w : 0.f;

    int beg = g_rowptr[v], end = g_rowptr[v + 1];
    for (int k = beg + grp; k < end; k += 4) {
        int s = g_csrsrc[k];
        xa = *(const float4*)&g_XL[s * 64 + fb];
        xb = *(const float4*)&g_XL[s * 64 + fb + 4];
        GAT_SCORE(e, xa, xb);
        float nm = fmaxf(m, e);
        float sc = ex2f(m - nm);
        float w  = ex2f(e - nm);
        l = fmaf(l, sc, w);
        aca.x = fmaf(aca.x, sc, w * xa.x);
        aca.y = fmaf(aca.y, sc, w * xa.y);
        aca.z = fmaf(aca.z, sc, w * xa.z);
        aca.w = fmaf(aca.w, sc, w * xa.w);
        acb.x = fmaf(acb.x, sc, w * xb.x);
        acb.y = fmaf(acb.y, sc, w * xb.y);
        acb.z = fmaf(acb.z, sc, w * xb.z);
        acb.w = fmaf(acb.w, sc, w * xb.w);
        m = nm;
    }
    __syncwarp();   // reconverge all 32 lanes before cross-group merge

    // merge the 4 groups (lanes g, g+8, g+16, g+24 share a feature block)
    float mo = fmaxf(m, __shfl_xor_sync(0xffffffffu, m, 8));
    mo = fmaxf(mo, __shfl_xor_sync(0xffffffffu, mo, 16));
    float wq = ex2f(m - mo);
    l *= wq;
    l += __shfl_xor_sync(0xffffffffu, l, 8);
    l += __shfl_xor_sync(0xffffffffu, l, 16);
#define GAT_MRG(R)                                    \
    R *= wq;                                          \
    R += __shfl_xor_sync(0xffffffffu, R, 8);          \
    R += __shfl_xor_sync(0xffffffffu, R, 16);
    GAT_MRG(aca.x) GAT_MRG(aca.y) GAT_MRG(aca.z) GAT_MRG(aca.w)
    GAT_MRG(acb.x) GAT_MRG(acb.y) GAT_MRG(acb.z) GAT_MRG(acb.w)
    float inv = 1.0f / l;

    __shared__ float shs[512], shq[512];
    if (g0) {
        float4 bia = *(const float4*)&gbias[fb];
        float4 bib = *(const float4*)&gbias[fb + 4];
        float4 rxa = *(const float4*)&g_X[v * 64 + fb];
        float4 rxb = *(const float4*)&g_X[v * 64 + fb + 4];
        float4 oa, ob;
        oa.x = fmaf(aca.x, inv, bia.x + rxa.x);
        oa.y = fmaf(aca.y, inv, bia.y + rxa.y);
        oa.z = fmaf(aca.z, inv, bia.z + rxa.z);
        oa.w = fmaf(aca.w, inv, bia.w + rxa.w);
        ob.x = fmaf(acb.x, inv, bib.x + rxb.x);
        ob.y = fmaf(acb.y, inv, bib.y + rxb.y);
        ob.z = fmaf(acb.z, inv, bib.z + rxb.z);
        ob.w = fmaf(acb.w, inv, bib.w + rxb.w);
        *(float4*)&g_H1R[v * 64 + fb]     = oa;
        *(float4*)&g_H1R[v * 64 + fb + 4] = ob;
        float4 qa, qb;
        qa.x = oa.x * oa.x; qa.y = oa.y * oa.y; qa.z = oa.z * oa.z; qa.w = oa.w * oa.w;
        qb.x = ob.x * ob.x; qb.y = ob.y * ob.y; qb.z = ob.z * ob.z; qb.w = ob.w * ob.w;
        *(float4*)&shs[warp * 64 + fb]     = oa;
        *(float4*)&shs[warp * 64 + fb + 4] = ob;
        *(float4*)&shq[warp * 64 + fb]     = qa;
        *(float4*)&shq[warp * 64 + fb + 4] = qb;
    }
    __syncthreads();
    int t = threadIdx.x;
    if (t < 64) {
        float S = 0.f, Q = 0.f;
#pragma unroll
        for (int w = 0; w < 8; w++) { S += shs[w * 64 + t]; Q += shq[w * 64 + t]; }
        g_part1[blockIdx.x * 128 + t]      = S;
        g_part1[blockIdx.x * 128 + 64 + t] = Q;
    }
}

// ---------------- BatchNorm reduce (from per-block partials) ---------------
template <int NB>
__device__ void stats_reduceN(const float* part, float* mu, float* istd, float* scr) {
    int t = threadIdx.x;
    int f = t & 63, c = t >> 6;
    float s = 0.f, q = 0.f;
    for (int b = c; b < NB; b += 4) {
        s += part[b * 128 + f];
        q += part[b * 128 + 64 + f];
    }
    scr[t] = s; scr[256 + t] = q;
    __syncthreads();
    if (t < 64) {
        float S = scr[t] + scr[t + 64] + scr[t + 128] + scr[t + 192];
        float Q = scr[256 + t] + scr[256 + t + 64] + scr[256 + t + 128] + scr[256 + t + 192];
        float m = S * (1.0f / NN);
        mu[t] = m;
        istd[t] = rsqrtf(Q * (1.0f / NN) - m * m + 1e-5f);
    }
    __syncthreads();
}

// OUT0 = bn1(H1R) + bn2(H2R)
__global__ void __launch_bounds__(256) k_combine(const float* __restrict__ g1, const float* __restrict__ b1,
                                                 const float* __restrict__ g2, const float* __restrict__ b2) {
    __shared__ float scr[512];
    __shared__ float mu1[64], is1[64], mu2[64], is2[64];
    stats_reduceN<512>(g_part1, mu1, is1, scr);
    stats_reduceN<128>(g_part2, mu2, is2, scr);
    int t = threadIdx.x;
    int base = blockIdx.x * 4096;
#pragma unroll
    for (int i = 0; i < 16; i++) {
        int o = base + t + i * 256;
        int f = o & 63;
        float v1 = (g_H1R[o] - mu1[f]) * is1[f] * g1[f] + b1[f];
        float v2 = (g_H2R[o] - mu2[f]) * is2[f] * g2[f] + b2[f];
        g_OUT0[o] = v1 + v2;
    }
}

// X = relu(bn3(OUT))
__global__ void __launch_bounds__(256) k_bn3relu(const float* __restrict__ g3, const float* __restrict__ b3) {
    __shared__ float scr[512];
    __shared__ float mu[64], is[64];
    stats_reduceN<128>(g_part3, mu, is, scr);
    int t = threadIdx.x;
    int base = blockIdx.x * 4096;
#pragma unroll
    for (int i = 0; i < 16; i++) {
        int o = base + t + i * 256;
        int f = o & 63;
        float v = (g_OUT[o] - mu[f]) * is[f] * g3[f] + b3[f];
        g_X[o] = fmaxf(v, 0.0f);
    }
}

// ---------------- global attention (flash, f32x2 + LDS.128 + packed-l) -----
// grid (32 q-tiles, 4 heads, NSPLIT key-splits), 128 threads (1 query/thread)
__global__ void __launch_bounds__(128) k_attn() {
    __shared__ __align__(16) float sK[256 * 16];
    __shared__ __align__(16) float sV[256 * 16];
    int tid = threadIdx.x;
    int q = blockIdx.x * 128 + tid;
    int h = blockIdx.y, sp = blockIdx.z;
    const float cs = 0.25f * 1.4426950408889634f;   // (1/sqrt(dh)) * log2(e)

    const float* KB = g_QKV + HH * NN * DHH;
    const float* VB = g_QKV + 2 * HH * NN * DHH;

    unsigned long long q2[8], o2[8];
    const float* qp = g_QKV + (h * NN + q) * DHH;
#pragma unroll
    for (int i = 0; i < 8; i++) {
        q2[i] = pk2(qp[2 * i] * cs, qp[2 * i + 1] * cs);
        o2[i] = 0ull;
    }
    float m = -1e30f;
    unsigned long long lacc0 = 0ull, lacc1 = 0ull;   // packed l accumulators

    const int keysPerSplit = NN / NSPLIT;            // 512
    for (int t = 0; t < keysPerSplit / 256; t++) {
        int base = sp * keysPerSplit + t * 256;
        __syncthreads();
        // coalesced staging from head-major K/V
        const float4* kg = (const float4*)(KB + (h * NN + base) * DHH);
        const float4* vg = (const float4*)(VB + (h * NN + base) * DHH);
        float4* sk4 = (float4*)sK;
        float4* sv4 = (float4*)sV;
#pragma unroll
        for (int u = 0; u < 8; u++) {
            sk4[u * 128 + tid] = kg[u * 128 + tid];
            sv4[u * 128 + tid] = vg[u * 128 + tid];
        }
        __syncthreads();
        const ulonglong2* k2 = (const ulonglong2*)sK;
        const ulonglong2* v2 = (const ulonglong2*)sV;

        for (int j0 = 0; j0 < 256; j0 += 16) {
            float s[16];
#pragma unroll
            for (int jj = 0; jj < 16; jj++) {
                ulonglong2 ka = k2[(j0 + jj) * 4 + 0];
                ulonglong2 kb = k2[(j0 + jj) * 4 + 1];
                ulonglong2 kc = k2[(j0 + jj) * 4 + 2];
                ulonglong2 kd = k2[(j0 + jj) * 4 + 3];
                unsigned long long acc = ffma2(q2[0], ka.x, 0ull);
                acc = ffma2(q2[1], ka.y, acc);
                acc = ffma2(q2[2], kb.x, acc);
                acc = ffma2(q2[3], kb.y, acc);
                acc = ffma2(q2[4], kc.x, acc);
                acc = ffma2(q2[5], kc.y, acc);
                acc = ffma2(q2[6], kd.x, acc);
                acc = ffma2(q2[7], kd.y, acc);
                float ax, ay;
                upk2(acc, ax, ay);
                s[jj] = ax + ay;
            }
            float cm = s[0];
#pragma unroll
            for (int jj = 1; jj < 16; jj++) cm = fmaxf(cm, s[jj]);
            if (cm > m) {                   // rescale only when the max rises
                float sc = ex2f(m - cm);
                m = cm;
                unsigned long long sc2 = pk2(sc, sc);
                lacc0 = fmul2(lacc0, sc2);
                lacc1 = fmul2(lacc1, sc2);
#pragma unroll
                for (int i = 0; i < 8; i++) o2[i] = fmul2(o2[i], sc2);
            }
            // independent MUFUs, then packed l accumulation (chain 16 -> 4)
            float p[16];
#pragma unroll
            for (int jj = 0; jj < 16; jj++) p[jj] = ex2f(s[jj] - m);
#pragma unroll
            for (int jj = 0; jj < 16; jj += 4) {
                lacc0 = fadd2(lacc0, pk2(p[jj], p[jj + 1]));
                lacc1 = fadd2(lacc1, pk2(p[jj + 2], p[jj + 3]));
            }
#pragma unroll
            for (int jj = 0; jj < 16; jj++) {
                unsigned long long p2 = pk2(p[jj], p[jj]);
                ulonglong2 va = v2[(j0 + jj) * 4 + 0];
                ulonglong2 vb = v2[(j0 + jj) * 4 + 1];
                ulonglong2 vc = v2[(j0 + jj) * 4 + 2];
                ulonglong2 vd = v2[(j0 + jj) * 4 + 3];
                o2[0] = ffma2(p2, va.x, o2[0]);
                o2[1] = ffma2(p2, va.y, o2[1]);
                o2[2] = ffma2(p2, vb.x, o2[2]);
                o2[3] = ffma2(p2, vb.y, o2[3]);
                o2[4] = ffma2(p2, vc.x, o2[4]);
                o2[5] = ffma2(p2, vc.y, o2[5]);
                o2[6] = ffma2(p2, vd.x, o2[6]);
                o2[7] = ffma2(p2, vd.y, o2[7]);
            }
        }
    }
    float l0x, l0y, l1x, l1y;
    upk2(lacc0, l0x, l0y);
    upk2(lacc1, l1x, l1y);
    float l = (l0x + l0y) + (l1x + l1y);

    int pidx = (h * NSPLIT + sp) * NN + q;
    g_mpart[pidx] = m;
    g_lpart[pidx] = l;
    float* op = g_opart + pidx * 16;
#pragma unroll
    for (int i = 0; i < 8; i++) {
        float x, y;
        upk2(o2[i], x, y);
        op[2 * i] = x;
        op[2 * i + 1] = y;
    }
}

// ---------------- pooling + classifier -------------------------------------
__global__ void k_bounds(const int* __restrict__ batch) {
    int t = threadIdx.x;
    if (t <= GG) {
        int lo = 0, hi = NN;
        while (lo < hi) {
            int mid = (lo + hi) >> 1;
            if (batch[mid] < t) lo = mid + 1; else hi = mid;
        }
        g_gbound[t] = lo;
    }
}

__global__ void __launch_bounds__(64) k_final(const float* __restrict__ fin_w,
                                              const float* __restrict__ fin_b,
                                              float* __restrict__ out) {
    int g = blockIdx.x, t = threadIdx.x;
    int s0 = g_gbound[g], s1 = g_gbound[g + 1];
    int cnt = s1 - s0;
    float s = 0.f;
    for (int r = s0; r < s1; r++) s += g_X[r * 64 + t];
    __shared__ float mean[64];
    __shared__ float lg[CC];
    __shared__ float lse;
    mean[t] = s / (float)max(cnt, 1);
    __syncthreads();
    if (t < CC) {
        float a = fin_b[t];
        for (int f = 0; f < 64; f++) a = fmaf(mean[f], fin_w[f * CC + t], a);
        lg[t] = a;
    }
    __syncthreads();
    if (t == 0) {
        float mx = lg[0];
        for (int c = 1; c < CC; c++) mx = fmaxf(mx, lg[c]);
        float se = 0.f;
        for (int c = 0; c < CC; c++) se += expf(lg[c] - mx);
        lse = mx + logf(se);
    }
    __syncthreads();
    if (t < CC) out[g * CC + t] = lg[t] - lse;
}

// ---------------- launch ----------------------------------------------------
extern "C" void kernel_launch(void* const* d_in, const int* in_sizes, int n_in,
                              void* d_out, int out_size) {
    const float* x         = (const float*)d_in[0];
    const int*   ei        = (const int*)d_in[1];
    const int*   batch     = (const int*)d_in[2];
    const float* pre_w1    = (const float*)d_in[3];
    const float* pre_b1    = (const float*)d_in[4];
    const float* pre_w2    = (const float*)d_in[5];
    const float* pre_b2    = (const float*)d_in[6];
    const float* gat_wl    = (const float*)d_in[7];
    const float* gat_bl    = (const float*)d_in[8];
    const float* gat_wr    = (const float*)d_in[9];
    const float* gat_br    = (const float*)d_in[10];
    const float* gat_att   = (const float*)d_in[11];
    const float* gat_bias  = (const float*)d_in[12];
    const float* attn_in_w = (const float*)d_in[13];
    const float* attn_in_b = (const float*)d_in[14];
    const float* attn_ow   = (const float*)d_in[15];
    const float* attn_ob   = (const float*)d_in[16];
    const float* bn1_g     = (const float*)d_in[17];
    const float* bn1_b     = (const float*)d_in[18];
    const float* bn2_g     = (const float*)d_in[19];
    const float* bn2_b     = (const float*)d_in[20];
    const float* bn3_g     = (const float*)d_in[21];
    const float* bn3_b     = (const float*)d_in[22];
    const float* mlp_w1    = (const float*)d_in[23];
    const float* mlp_b1    = (const float*)d_in[24];
    const float* mlp_w2    = (const float*)d_in[25];
    const float* mlp_b2    = (const float*)d_in[26];
    const float* fin_w     = (const float*)d_in[27];
    const float* fin_b     = (const float*)d_in[28];

    // CSR of incoming edges (same every layer)
    k_zero_cnt<<<16, 256>>>();
    k_hist<<<EE / 256, 256>>>(ei);
    k_scan<<<1, 1024>>>();
    k_scatter<<<EE / 256, 256>>>(ei);

    // preprocess MLP
    k_gemm<1, false, false, -1, false, false, false, false><<<dim3(128, 2), 256>>>(
        x, -1, pre_w1, pre_b1, -1, 1, 128, 9, nullptr, nullptr, 0);
    k_gemm<1, false, false, -1, false, false, false, true><<<dim3(128, 1), 256>>>(
        nullptr, 1, pre_w2, pre_b2, -1, 0, 64, 128, nullptr, nullptr, 0);

    for (int l = 0; l < LL; l++) {
        // local GATv2: xl+xr in ONE dual launch, then fused one-pass GAT
        k_gemm<0, false, false, -1, false, false, true, true><<<dim3(128, 2), 256>>>(
            nullptr, 0, gat_wl + l * 64 * 64, gat_bl + l * 64, -1, 2, 64, 64,
            gat_wr + l * 64 * 64, gat_br + l * 64, 3);
        k_gat<<<512, 256>>>(gat_att + l * 64, gat_bias + l * 64);

        // global attention (QKV in head-major layout)
        k_gemm<0, true, false, -1, true, false, false, true><<<dim3(128, 3), 256>>>(
            nullptr, 0, attn_in_w + l * 192 * 64, attn_in_b + l * 192, -1, 8, 192, 64,
            nullptr, nullptr, 0);
        k_attn<<<dim3(32, 4, NSPLIT), 128>>>();
        // out proj with split-merge fused into A-load + residual + BN2 partials
        k_gemm<0, true, true, 2, false, true, false, true><<<dim3(128, 1), 256>>>(
            nullptr, -1, attn_ow + l * 64 * 64, attn_ob + l * 64, 0, 5, 64, 64,
            nullptr, nullptr, 0);

        // combine (bn1 + bn2) + MLP + norm3
        k_combine<<<64, 256>>>(bn1_g + l * 64, bn1_b + l * 64, bn2_g + l * 64, bn2_b + l * 64);
        k_gemm<2, false, false, -1, false, false, false, true><<<dim3(128, 2), 256>>>(
            nullptr, 6, mlp_w1 + l * 64 * 128, mlp_b1 + l * 128, -1, 1, 128, 64,
            nullptr, nullptr, 0);
        k_gemm<0, false, true, 3, false, false, false, true><<<dim3(128, 1), 256>>>(
            nullptr, 1, mlp_w2 + l * 128 * 64, mlp_b2 + l * 64, 6, 7, 64, 128,
            nullptr, nullptr, 0);
        k_bn3relu<<<64, 256>>>(bn3_g + l * 64, bn3_b + l * 64);
    }

    // pooling + classifier
    k_bounds<<<1, 128>>>(batch);
    k_final<<<GG, 64>>>(fin_w, fin_b, (float*)d_out);
}

// round 15
// speedup vs baseline: 1.4415x; 1.4415x over previous
#include <cuda_runtime.h>
#include <math.h>

// ---------------- problem constants (fixed by setup_inputs) ----------------
#define NN 4096       // nodes
#define EE 262144     // edges
#define DD 64         // hidden dim
#define LL 3          // layers
#define HH 4          // attention heads
#define DHH 16        // head dim
#define GG 64         // graphs
#define CC 10         // classes
#define NSPLIT 4      // attention key splits

// ---------------- device global scratch (allowed: no runtime alloc) --------
__device__ float g_X   [NN * DD];
__device__ float g_T128[NN * 128];
__device__ float g_XL  [NN * DD];
__device__ float g_XR  [NN * DD];
__device__ float g_H1R [NN * DD];
__device__ float g_H2R [NN * DD];
__device__ float g_OUT0[NN * DD];
__device__ float g_OUT [NN * DD];
__device__ float g_QKV [3 * HH * NN * DHH];   // head-major: [which][h][n][16]

__device__ int g_cnt   [NN];
__device__ int g_rowptr[NN + 1];
__device__ int g_cursor[NN];
__device__ int g_csrsrc[EE];

// BN partial sums: [block][0..63]=sum, [block][64..127]=sumsq
__device__ float g_part1[512 * 128];   // H1R stats (from k_gat, 512 blocks)
__device__ float g_part2[128 * 128];   // H2R stats (from attn_out gemm, 128 blocks)
__device__ float g_part3[128 * 128];   // OUT stats (from mlp2 gemm, 128 blocks)

// attention split partials: 4 heads x NSPLIT splits
__device__ float g_opart[HH * NSPLIT * NN * DHH];
__device__ float g_mpart[HH * NSPLIT * NN];
__device__ float g_lpart[HH * NSPLIT * NN];

__device__ int g_gbound[GG + 1];

// ---------------- f32x2 packed + fast exp2 helpers (sm_10x) ----------------
__device__ __forceinline__ unsigned long long pk2(float x, float y) {
    unsigned long long r;
    asm("mov.b64 %0, {%1, %2};" : "=l"(r) : "f"(x), "f"(y));
    return r;
}
__device__ __forceinline__ void upk2(unsigned long long v, float& x, float& y) {
    asm("mov.b64 {%0, %1}, %2;" : "=f"(x), "=f"(y) : "l"(v));
}
__device__ __forceinline__ unsigned long long ffma2(unsigned long long a, unsigned long long b,
                                                    unsigned long long c) {
    unsigned long long d;
    asm("fma.rn.f32x2 %0, %1, %2, %3;" : "=l"(d) : "l"(a), "l"(b), "l"(c));
    return d;
}
__device__ __forceinline__ unsigned long long fmul2(unsigned long long a, unsigned long long b) {
    unsigned long long d;
    asm("mul.rn.f32x2 %0, %1, %2;" : "=l"(d) : "l"(a), "l"(b));
    return d;
}
__device__ __forceinline__ unsigned long long fadd2(unsigned long long a, unsigned long long b) {
    unsigned long long d;
    asm("add.rn.f32x2 %0, %1, %2;" : "=l"(d) : "l"(a), "l"(b));
    return d;
}
// single MUFU.EX2 — exp2f without fast-math is a multi-instruction routine
__device__ __forceinline__ float ex2f(float x) {
    float y;
    asm("ex2.approx.f32 %0, %1;" : "=f"(y) : "f"(x));
    return y;
}

__device__ __forceinline__ float gelu_exact(float v) {
    return 0.5f * v * (1.0f + erff(v * 0.70710678118654752440f));
}

// buffer selector (host cannot take addresses of __device__ globals)
__device__ __forceinline__ float* bufsel(int id) {
    switch (id) {
        case 0: return g_X;
        case 1: return g_T128;
        case 2: return g_XL;
        case 3: return g_XR;
        case 4: return g_H1R;
        case 5: return g_H2R;
        case 6: return g_OUT0;
        case 7: return g_OUT;
        case 8: return g_QKV;
    }
    return nullptr;
}
__device__ __forceinline__ float* partsel(int id) {
    return (id == 2) ? g_part2 : g_part3;
}

// ---------------- CSR build ------------------------------------------------
__global__ void k_zero_cnt() {
    int t = blockIdx.x * blockDim.x + threadIdx.x;
    if (t < NN) g_cnt[t] = 0;
}

__global__ void k_hist(const int* __restrict__ ei) {
    int e = blockIdx.x * blockDim.x + threadIdx.x;
    if (e < EE) atomicAdd(&g_cnt[ei[EE + e]], 1);
}

__global__ void k_scan() {
    __shared__ int sh[1024];
    int t = threadIdx.x;
    int c0 = g_cnt[4 * t], c1 = g_cnt[4 * t + 1], c2 = g_cnt[4 * t + 2], c3 = g_cnt[4 * t + 3];
    int tot = c0 + c1 + c2 + c3;
    sh[t] = tot;
    __syncthreads();
    for (int off = 1; off < 1024; off <<= 1) {
        int v = 0;
        if (t >= off) v = sh[t - off];
        __syncthreads();
        sh[t] += v;
        __syncthreads();
    }
    int excl = sh[t] - tot;
    int p0 = excl, p1 = excl + c0, p2 = p1 + c1, p3 = p2 + c2;
    g_rowptr[4 * t] = p0; g_rowptr[4 * t + 1] = p1;
    g_rowptr[4 * t + 2] = p2; g_rowptr[4 * t + 3] = p3;
    g_cursor[4 * t] = p0; g_cursor[4 * t + 1] = p1;
    g_cursor[4 * t + 2] = p2; g_cursor[4 * t + 3] = p3;
    if (t == 1023) g_rowptr[NN] = p3 + c3;
}

__global__ void k_scatter(const int* __restrict__ ei) {
    int e = blockIdx.x * blockDim.x + threadIdx.x;
    if (e < EE) {
        int d = ei[EE + e];
        int pos = atomicAdd(&g_cursor[d], 1);
        g_csrsrc[pos] = ei[e];
    }
}

// ---------------- generic small SGEMM (4096 rows) ---------------------------
// C[row, n0+col] = act( sum_k A[row,k]*B(k,col) + bias[col] (+ res[row,col]) )
// ACT: 0 none, 1 gelu, 2 relu.  TB: B given as [Ntot, K] (use B^T).
// STATS >= 0: emit per-block column sum/sumsq partials (y==1, Ntot==64).
// QKVOUT: store to head-major g_QKV layout.
// MERGEA: A tile = attention split-merge of this block's rows (K==64).
// DUAL: blockIdx.y selects (B,bias,out) vs (B2,bias2,out2); n0=0.
template <int ACT, bool TB, bool RES, int STATS, bool QKVOUT, bool MERGEA, bool DUAL>
__global__ void __launch_bounds__(256) k_gemm(const float* __restrict__ Aext, int aSel,
                                              const float* __restrict__ B,
                                              const float* __restrict__ bias,
                                              int resSel, int cSel, int Ntot, int K,
                                              const float* __restrict__ B2,
                                              const float* __restrict__ bias2,
                                              int cSel2) {
    __shared__ float As[32 * 128];
    __shared__ float Bs[128 * 64];
    const float* A = (aSel >= 0) ? bufsel(aSel) : Aext;
    float* Cm;
    if (DUAL) {
        if (blockIdx.y == 1) { B = B2; bias = bias2; Cm = bufsel(cSel2); }
        else                 { Cm = bufsel(cSel); }
    } else {
        Cm = bufsel(cSel);
    }
    const float* res = RES ? bufsel(resSel) : nullptr;

    int rb = blockIdx.x * 32;
    int n0 = DUAL ? 0 : blockIdx.y * 64;
    int tid = threadIdx.x;

    if (MERGEA) {
        // A tile = merged attention output for rows rb..rb+31 (K == 64)
        if (tid < 128) {
            int r = tid >> 2, h = tid & 3, q = rb + r;
            float mv[NSPLIT], mb = -1e30f;
#pragma unroll
            for (int sp = 0; sp < NSPLIT; sp++) {
                mv[sp] = g_mpart[(h * NSPLIT + sp) * NN + q];
                mb = fmaxf(mb, mv[sp]);
            }
            float L = 0.f, o[16] = {};
#pragma unroll
            for (int sp = 0; sp < NSPLIT; sp++) {
                float w = ex2f(mv[sp] - mb);
                int pidx = (h * NSPLIT + sp) * NN + q;
                L += g_lpart[pidx] * w;
                const float4* op4 = (const float4*)(g_opart + pidx * 16);
#pragma unroll
                for (int i = 0; i < 4; i++) {
                    float4 vv = op4[i];
                    o[4 * i + 0] = fmaf(vv.x, w, o[4 * i + 0]);
                    o[4 * i + 1] = fmaf(vv.y, w, o[4 * i + 1]);
                    o[4 * i + 2] = fmaf(vv.z, w, o[4 * i + 2]);
                    o[4 * i + 3] = fmaf(vv.w, w, o[4 * i + 3]);
                }
            }
            float inv = 1.0f / L;
#pragma unroll
            for (int d = 0; d < 16; d++) As[r * 64 + h * 16 + d] = o[d] * inv;
        }
    } else {
        for (int idx = tid; idx < 32 * K; idx += 256) As[idx] = A[rb * K + idx];
    }
    for (int idx = tid; idx < K * 64; idx += 256) {
        if (TB) {
            int n = idx / K;
            int k = idx - n * K;
            Bs[k * 64 + n] = B[(n0 + n) * K + k];
        } else {
            int k = idx >> 6;
            int n = idx & 63;
            Bs[k * 64 + n] = B[k * Ntot + n0 + n];
        }
    }
    __syncthreads();

    int tr = tid >> 4;       // 0..15 (rows tr, tr+16)
    int tc = tid & 15;       // 0..15 (cols tc*4..tc*4+3)
    float acc[2][4] = {};
    for (int k = 0; k < K; k++) {
        float a0 = As[tr * K + k];
        float a1 = As[(tr + 16) * K + k];
        float4 b = *(const float4*)&Bs[k * 64 + tc * 4];
        acc[0][0] = fmaf(a0, b.x, acc[0][0]);
        acc[0][1] = fmaf(a0, b.y, acc[0][1]);
        acc[0][2] = fmaf(a0, b.z, acc[0][2]);
        acc[0][3] = fmaf(a0, b.w, acc[0][3]);
        acc[1][0] = fmaf(a1, b.x, acc[1][0]);
        acc[1][1] = fmaf(a1, b.y, acc[1][1]);
        acc[1][2] = fmaf(a1, b.z, acc[1][2]);
        acc[1][3] = fmaf(a1, b.w, acc[1][3]);
    }
    float sl[4] = {}, ql[4] = {};
#pragma unroll
    for (int r = 0; r < 2; r++) {
        int row = rb + tr + r * 16;
#pragma unroll
        for (int i = 0; i < 4; i++) {
            int col = n0 + tc * 4 + i;
            float v = acc[r][i] + bias[col];
            if (RES) v += res[row * Ntot + col];
            if (ACT == 1) v = gelu_exact(v);
            if (ACT == 2) v = fmaxf(v, 0.0f);
            if (QKVOUT) {
                int which = col >> 6, hh = (col >> 4) & 3, d = col & 15;
                g_QKV[which * (HH * NN * DHH) + (hh * NN + row) * DHH + d] = v;
            } else {
                Cm[row * Ntot + col] = v;
            }
            if (STATS >= 0) { sl[i] += v; ql[i] = fmaf(v, v, ql[i]); }
        }
    }
    if (STATS >= 0) {
        __syncthreads();   // done with As main-loop reads
#pragma unroll
        for (int i = 0; i < 4; i++) {
            As[tr * 128 + tc * 4 + i]      = sl[i];
            As[tr * 128 + 64 + tc * 4 + i] = ql[i];
        }
        __syncthreads();
        if (tid < 128) {
            float S = 0.f;
#pragma unroll
            for (int r = 0; r < 16; r++) S += As[r * 128 + tid];
            partsel(STATS)[blockIdx.x * 128 + tid] = S;
        }
    }
}

// ---------------- GATv2: fused one-pass, 4 edge-groups x 8 lanes -----------
// warp = one dst node; lanes split into 4 groups of 8; each group runs an
// independent online softmax over every 4th edge; groups merged via shfl.
// Edge loop software-prefetches the next source row to hide L2 latency.
__global__ void __launch_bounds__(256) k_gat(const float* __restrict__ att,
                                             const float* __restrict__ gbias) {
    const float L2E = 1.4426950408889634f;
    int warp = threadIdx.x >> 5, lane = threadIdx.x & 31;
    int grp = lane >> 3;
    unsigned gm = 0xFFu << (grp * 8);   // group-local shuffle mask
    int fb = (lane & 7) * 8;            // feature block [fb, fb+8)
    int v = blockIdx.x * 8 + warp;

    float4 xra = *(const float4*)&g_XR[v * 64 + fb];
    float4 xrb = *(const float4*)&g_XR[v * 64 + fb + 4];
    float4 ata = *(const float4*)&att[fb];
    float4 atb = *(const float4*)&att[fb + 4];
    ata.x *= L2E; ata.y *= L2E; ata.z *= L2E; ata.w *= L2E;
    atb.x *= L2E; atb.y *= L2E; atb.z *= L2E; atb.w *= L2E;

#define GAT_SCORE(E, XA, XB)                                                  \
    {                                                                         \
        float z, p = 0.f;                                                     \
        z = XA.x + xra.x; z = fmaxf(z, 0.2f * z); p = fmaf(z, ata.x, p);      \
        z = XA.y + xra.y; z = fmaxf(z, 0.2f * z); p = fmaf(z, ata.y, p);      \
        z = XA.z + xra.z; z = fmaxf(z, 0.2f * z); p = fmaf(z, ata.z, p);      \
        z = XA.w + xra.w; z = fmaxf(z, 0.2f * z); p = fmaf(z, ata.w, p);      \
        z = XB.x + xrb.x; z = fmaxf(z, 0.2f * z); p = fmaf(z, atb.x, p);      \
        z = XB.y + xrb.y; z = fmaxf(z, 0.2f * z); p = fmaf(z, atb.y, p);      \
        z = XB.z + xrb.z; z = fmaxf(z, 0.2f * z); p = fmaf(z, atb.z, p);      \
        z = XB.w + xrb.w; z = fmaxf(z, 0.2f * z); p = fmaf(z, atb.w, p);      \
        p += __shfl_xor_sync(gm, p, 1);                                       \
        p += __shfl_xor_sync(gm, p, 2);                                       \
        p += __shfl_xor_sync(gm, p, 4);                                       \
        E = p;                                                                \
    }

    // self-loop seeds group 0; other groups start empty (m=-inf, l=0, acc=0)
    float4 xa = *(const float4*)&g_XL[v * 64 + fb];
    float4 xb = *(const float4*)&g_XL[v * 64 + fb + 4];
    float e;
    GAT_SCORE(e, xa, xb);
    bool g0 = (grp == 0);
    float m = g0 ? e : -1e30f;
    float l = g0 ? 1.f : 0.f;
    float4 aca, acb;
    aca.x = g0 ? xa.x : 0.f; aca.y = g0 ? xa.y : 0.f;
    aca.z = g0 ? xa.z : 0.f; aca.w = g0 ? xa.w : 0.f;
    acb.x = g0 ? xb.x : 0.f; acb.y = g0 ? xb.y : 0.f;
    acb.z = g0 ? xb.z : 0.f; acb.w = g0 ? xb.w : 0.f;

    int beg = g_rowptr[v], end = g_rowptr[v + 1];
    int k = beg + grp;
    if (k < end) {
        // prime: loads for the first edge of this group
        int s = g_csrsrc[k];
        float4 nxa = *(const float4*)&g_XL[s * 64 + fb];
        float4 nxb = *(const float4*)&g_XL[s * 64 + fb + 4];
        while (true) {
            xa = nxa; xb = nxb;
            int kn = k + 4;
            // prefetch next edge BEFORE the shfl/mufu chain of this one
            if (kn < end) {      // group-uniform branch
                int sn = g_csrsrc[kn];
                nxa = *(const float4*)&g_XL[sn * 64 + fb];
                nxb = *(const float4*)&g_XL[sn * 64 + fb + 4];
            }
            GAT_SCORE(e, xa, xb);
            float nm = fmaxf(m, e);
            float sc = ex2f(m - nm);
            float w  = ex2f(e - nm);
            l = fmaf(l, sc, w);
            aca.x = fmaf(aca.x, sc, w * xa.x);
            aca.y = fmaf(aca.y, sc, w * xa.y);
            aca.z = fmaf(aca.z, sc, w * xa.z);
            aca.w = fmaf(aca.w, sc, w * xa.w);
            acb.x = fmaf(acb.x, sc, w * xb.x);
            acb.y = fmaf(acb.y, sc, w * xb.y);
            acb.z = fmaf(acb.z, sc, w * xb.z);
            acb.w = fmaf(acb.w, sc, w * xb.w);
            m = nm;
            k = kn;
            if (k >= end) break;
        }
    }
    __syncwarp();   // reconverge all 32 lanes before cross-group merge

    // merge the 4 groups (lanes g, g+8, g+16, g+24 share a feature block)
    float mo = fmaxf(m, __shfl_xor_sync(0xffffffffu, m, 8));
    mo = fmaxf(mo, __shfl_xor_sync(0xffffffffu, mo, 16));
    float wq = ex2f(m - mo);
    l *= wq;
    l += __shfl_xor_sync(0xffffffffu, l, 8);
    l += __shfl_xor_sync(0xffffffffu, l, 16);
#define GAT_MRG(R)                                    \
    R *= wq;                                          \
    R += __shfl_xor_sync(0xffffffffu, R, 8);          \
    R += __shfl_xor_sync(0xffffffffu, R, 16);
    GAT_MRG(aca.x) GAT_MRG(aca.y) GAT_MRG(aca.z) GAT_MRG(aca.w)
    GAT_MRG(acb.x) GAT_MRG(acb.y) GAT_MRG(acb.z) GAT_MRG(acb.w)
    float inv = 1.0f / l;

    __shared__ float shs[512], shq[512];
    if (g0) {
        float4 bia = *(const float4*)&gbias[fb];
        float4 bib = *(const float4*)&gbias[fb + 4];
        float4 rxa = *(const float4*)&g_X[v * 64 + fb];
        float4 rxb = *(const float4*)&g_X[v * 64 + fb + 4];
        float4 oa, ob;
        oa.x = fmaf(aca.x, inv, bia.x + rxa.x);
        oa.y = fmaf(aca.y, inv, bia.y + rxa.y);
        oa.z = fmaf(aca.z, inv, bia.z + rxa.z);
        oa.w = fmaf(aca.w, inv, bia.w + rxa.w);
        ob.x = fmaf(acb.x, inv, bib.x + rxb.x);
        ob.y = fmaf(acb.y, inv, bib.y + rxb.y);
        ob.z = fmaf(acb.z, inv, bib.z + rxb.z);
        ob.w = fmaf(acb.w, inv, bib.w + rxb.w);
        *(float4*)&g_H1R[v * 64 + fb]     = oa;
        *(float4*)&g_H1R[v * 64 + fb + 4] = ob;
        float4 qa, qb;
        qa.x = oa.x * oa.x; qa.y = oa.y * oa.y; qa.z = oa.z * oa.z; qa.w = oa.w * oa.w;
        qb.x = ob.x * ob.x; qb.y = ob.y * ob.y; qb.z = ob.z * ob.z; qb.w = ob.w * ob.w;
        *(float4*)&shs[warp * 64 + fb]     = oa;
        *(float4*)&shs[warp * 64 + fb + 4] = ob;
        *(float4*)&shq[warp * 64 + fb]     = qa;
        *(float4*)&shq[warp * 64 + fb + 4] = qb;
    }
    __syncthreads();
    int t = threadIdx.x;
    if (t < 64) {
        float S = 0.f, Q = 0.f;
#pragma unroll
        for (int w = 0; w < 8; w++) { S += shs[w * 64 + t]; Q += shq[w * 64 + t]; }
        g_part1[blockIdx.x * 128 + t]      = S;
        g_part1[blockIdx.x * 128 + 64 + t] = Q;
    }
}

// ---------------- BatchNorm reduce (from per-block partials) ---------------
template <int NB>
__device__ void stats_reduceN(const float* part, float* mu, float* istd, float* scr) {
    int t = threadIdx.x;
    int f = t & 63, c = t >> 6;
    float s = 0.f, q = 0.f;
    for (int b = c; b < NB; b += 4) {
        s += part[b * 128 + f];
        q += part[b * 128 + 64 + f];
    }
    scr[t] = s; scr[256 + t] = q;
    __syncthreads();
    if (t < 64) {
        float S = scr[t] + scr[t + 64] + scr[t + 128] + scr[t + 192];
        float Q = scr[256 + t] + scr[256 + t + 64] + scr[256 + t + 128] + scr[256 + t + 192];
        float m = S * (1.0f / NN);
        mu[t] = m;
        istd[t] = rsqrtf(Q * (1.0f / NN) - m * m + 1e-5f);
    }
    __syncthreads();
}

// OUT0 = bn1(H1R) + bn2(H2R)
__global__ void __launch_bounds__(256) k_combine(const float* __restrict__ g1, const float* __restrict__ b1,
                                                 const float* __restrict__ g2, const float* __restrict__ b2) {
    __shared__ float scr[512];
    __shared__ float mu1[64], is1[64], mu2[64], is2[64];
    stats_reduceN<512>(g_part1, mu1, is1, scr);
    stats_reduceN<128>(g_part2, mu2, is2, scr);
    int t = threadIdx.x;
    int base = blockIdx.x * 4096;
#pragma unroll
    for (int i = 0; i < 16; i++) {
        int o = base + t + i * 256;
        int f = o & 63;
        float v1 = (g_H1R[o] - mu1[f]) * is1[f] * g1[f] + b1[f];
        float v2 = (g_H2R[o] - mu2[f]) * is2[f] * g2[f] + b2[f];
        g_OUT0[o] = v1 + v2;
    }
}

// X = relu(bn3(OUT))
__global__ void __launch_bounds__(256) k_bn3relu(const float* __restrict__ g3, const float* __restrict__ b3) {
    __shared__ float scr[512];
    __shared__ float mu[64], is[64];
    stats_reduceN<128>(g_part3, mu, is, scr);
    int t = threadIdx.x;
    int base = blockIdx.x * 4096;
#pragma unroll
    for (int i = 0; i < 16; i++) {
        int o = base + t + i * 256;
        int f = o & 63;
        float v = (g_OUT[o] - mu[f]) * is[f] * g3[f] + b3[f];
        g_X[o] = fmaxf(v, 0.0f);
    }
}

// ---------------- global attention (flash, f32x2 + LDS.128 + packed-l) -----
// grid (32 q-tiles, 4 heads, NSPLIT key-splits), 128 threads (1 query/thread)
__global__ void __launch_bounds__(128) k_attn() {
    __shared__ __align__(16) float sK[256 * 16];
    __shared__ __align__(16) float sV[256 * 16];
    int tid = threadIdx.x;
    int q = blockIdx.x * 128 + tid;
    int h = blockIdx.y, sp = blockIdx.z;
    const float cs = 0.25f * 1.4426950408889634f;   // (1/sqrt(dh)) * log2(e)

    const float* KB = g_QKV + HH * NN * DHH;
    const float* VB = g_QKV + 2 * HH * NN * DHH;

    unsigned long long q2[8], o2[8];
    const float* qp = g_QKV + (h * NN + q) * DHH;
#pragma unroll
    for (int i = 0; i < 8; i++) {
        q2[i] = pk2(qp[2 * i] * cs, qp[2 * i + 1] * cs);
        o2[i] = 0ull;
    }
    float m = -1e30f;
    unsigned long long lacc0 = 0ull, lacc1 = 0ull;   // packed l accumulators

    const int keysPerSplit = NN / NSPLIT;            // 1024
    for (int t = 0; t < keysPerSplit / 256; t++) {
        int base = sp * keysPerSplit + t * 256;
        __syncthreads();
        // coalesced staging from head-major K/V
        const float4* kg = (const float4*)(KB + (h * NN + base) * DHH);
        const float4* vg = (const float4*)(VB + (h * NN + base) * DHH);
        float4* sk4 = (float4*)sK;
        float4* sv4 = (float4*)sV;
#pragma unroll
        for (int u = 0; u < 8; u++) {
            sk4[u * 128 + tid] = kg[u * 128 + tid];
            sv4[u * 128 + tid] = vg[u * 128 + tid];
        }
        __syncthreads();
        const ulonglong2* k2 = (const ulonglong2*)sK;
        const ulonglong2* v2 = (const ulonglong2*)sV;

        for (int j0 = 0; j0 < 256; j0 += 16) {
            float s[16];
#pragma unroll
            for (int jj = 0; jj < 16; jj++) {
                ulonglong2 ka = k2[(j0 + jj) * 4 + 0];
                ulonglong2 kb = k2[(j0 + jj) * 4 + 1];
                ulonglong2 kc = k2[(j0 + jj) * 4 + 2];
                ulonglong2 kd = k2[(j0 + jj) * 4 + 3];
                unsigned long long acc = ffma2(q2[0], ka.x, 0ull);
                acc = ffma2(q2[1], ka.y, acc);
                acc = ffma2(q2[2], kb.x, acc);
                acc = ffma2(q2[3], kb.y, acc);
                acc = ffma2(q2[4], kc.x, acc);
                acc = ffma2(q2[5], kc.y, acc);
                acc = ffma2(q2[6], kd.x, acc);
                acc = ffma2(q2[7], kd.y, acc);
                float ax, ay;
                upk2(acc, ax, ay);
                s[jj] = ax + ay;
            }
            float cm = s[0];
#pragma unroll
            for (int jj = 1; jj < 16; jj++) cm = fmaxf(cm, s[jj]);
            if (cm > m) {                   // rescale only when the max rises
                float sc = ex2f(m - cm);
                m = cm;
                unsigned long long sc2 = pk2(sc, sc);
                lacc0 = fmul2(lacc0, sc2);
                lacc1 = fmul2(lacc1, sc2);
#pragma unroll
                for (int i = 0; i < 8; i++) o2[i] = fmul2(o2[i], sc2);
            }
            // independent MUFUs, then packed l accumulation (chain 16 -> 4)
            float p[16];
#pragma unroll
            for (int jj = 0; jj < 16; jj++) p[jj] = ex2f(s[jj] - m);
#pragma unroll
            for (int jj = 0; jj < 16; jj += 4) {
                lacc0 = fadd2(lacc0, pk2(p[jj], p[jj + 1]));
                lacc1 = fadd2(lacc1, pk2(p[jj + 2], p[jj + 3]));
            }
#pragma unroll
            for (int jj = 0; jj < 16; jj++) {
                unsigned long long p2 = pk2(p[jj], p[jj]);
                ulonglong2 va = v2[(j0 + jj) * 4 + 0];
                ulonglong2 vb = v2[(j0 + jj) * 4 + 1];
                ulonglong2 vc = v2[(j0 + jj) * 4 + 2];
                ulonglong2 vd = v2[(j0 + jj) * 4 + 3];
                o2[0] = ffma2(p2, va.x, o2[0]);
                o2[1] = ffma2(p2, va.y, o2[1]);
                o2[2] = ffma2(p2, vb.x, o2[2]);
                o2[3] = ffma2(p2, vb.y, o2[3]);
                o2[4] = ffma2(p2, vc.x, o2[4]);
                o2[5] = ffma2(p2, vc.y, o2[5]);
                o2[6] = ffma2(p2, vd.x, o2[6]);
                o2[7] = ffma2(p2, vd.y, o2[7]);
            }
        }
    }
    float l0x, l0y, l1x, l1y;
    upk2(lacc0, l0x, l0y);
    upk2(lacc1, l1x, l1y);
    float l = (l0x + l0y) + (l1x + l1y);

    int pidx = (h * NSPLIT + sp) * NN + q;
    g_mpart[pidx] = m;
    g_lpart[pidx] = l;
    float* op = g_opart + pidx * 16;
#pragma unroll
    for (int i = 0; i < 8; i++) {
        float x, y;
        upk2(o2[i], x, y);
        op[2 * i] = x;
        op[2 * i + 1] = y;
    }
}

// ---------------- pooling + classifier -------------------------------------
__global__ void k_bounds(const int* __restrict__ batch) {
    int t = threadIdx.x;
    if (t <= GG) {
        int lo = 0, hi = NN;
        while (lo < hi) {
            int mid = (lo + hi) >> 1;
            if (batch[mid] < t) lo = mid + 1; else hi = mid;
        }
        g_gbound[t] = lo;
    }
}

__global__ void __launch_bounds__(64) k_final(const float* __restrict__ fin_w,
                                              const float* __restrict__ fin_b,
                                              float* __restrict__ out) {
    int g = blockIdx.x, t = threadIdx.x;
    int s0 = g_gbound[g], s1 = g_gbound[g + 1];
    int cnt = s1 - s0;
    float s = 0.f;
    for (int r = s0; r < s1; r++) s += g_X[r * 64 + t];
    __shared__ float mean[64];
    __shared__ float lg[CC];
    __shared__ float lse;
    mean[t] = s / (float)max(cnt, 1);
    __syncthreads();
    if (t < CC) {
        float a = fin_b[t];
        for (int f = 0; f < 64; f++) a = fmaf(mean[f], fin_w[f * CC + t], a);
        lg[t] = a;
    }
    __syncthreads();
    if (t == 0) {
        float mx = lg[0];
        for (int c = 1; c < CC; c++) mx = fmaxf(mx, lg[c]);
        float se = 0.f;
        for (int c = 0; c < CC; c++) se += expf(lg[c] - mx);
        lse = mx + logf(se);
    }
    __syncthreads();
    if (t < CC) out[g * CC + t] = lg[t] - lse;
}

// ---------------- launch ----------------------------------------------------
extern "C" void kernel_launch(void* const* d_in, const int* in_sizes, int n_in,
                              void* d_out, int out_size) {
    const float* x         = (const float*)d_in[0];
    const int*   ei        = (const int*)d_in[1];
    const int*   batch     = (const int*)d_in[2];
    const float* pre_w1    = (const float*)d_in[3];
    const float* pre_b1    = (const float*)d_in[4];
    const float* pre_w2    = (const float*)d_in[5];
    const float* pre_b2    = (const float*)d_in[6];
    const float* gat_wl    = (const float*)d_in[7];
    const float* gat_bl    = (const float*)d_in[8];
    const float* gat_wr    = (const float*)d_in[9];
    const float* gat_br    = (const float*)d_in[10];
    const float* gat_att   = (const float*)d_in[11];
    const float* gat_bias  = (const float*)d_in[12];
    const float* attn_in_w = (const float*)d_in[13];
    const float* attn_in_b = (const float*)d_in[14];
    const float* attn_ow   = (const float*)d_in[15];
    const float* attn_ob   = (const float*)d_in[16];
    const float* bn1_g     = (const float*)d_in[17];
    const float* bn1_b     = (const float*)d_in[18];
    const float* bn2_g     = (const float*)d_in[19];
    const float* bn2_b     = (const float*)d_in[20];
    const float* bn3_g     = (const float*)d_in[21];
    const float* bn3_b     = (const float*)d_in[22];
    const float* mlp_w1    = (const float*)d_in[23];
    const float* mlp_b1    = (const float*)d_in[24];
    const float* mlp_w2    = (const float*)d_in[25];
    const float* mlp_b2    = (const float*)d_in[26];
    const float* fin_w     = (const float*)d_in[27];
    const float* fin_b     = (const float*)d_in[28];

    // CSR of incoming edges (same every layer)
    k_zero_cnt<<<16, 256>>>();
    k_hist<<<EE / 256, 256>>>(ei);
    k_scan<<<1, 1024>>>();
    k_scatter<<<EE / 256, 256>>>(ei);

    // preprocess MLP
    k_gemm<1, false, false, -1, false, false, false><<<dim3(128, 2), 256>>>(
        x, -1, pre_w1, pre_b1, -1, 1, 128, 9, nullptr, nullptr, 0);
    k_gemm<1, false, false, -1, false, false, false><<<dim3(128, 1), 256>>>(
        nullptr, 1, pre_w2, pre_b2, -1, 0, 64, 128, nullptr, nullptr, 0);

    for (int l = 0; l < LL; l++) {
        // local GATv2: xl+xr in ONE dual launch, then fused one-pass GAT
        k_gemm<0, false, false, -1, false, false, true><<<dim3(128, 2), 256>>>(
            nullptr, 0, gat_wl + l * 64 * 64, gat_bl + l * 64, -1, 2, 64, 64,
            gat_wr + l * 64 * 64, gat_br + l * 64, 3);
        k_gat<<<512, 256>>>(gat_att + l * 64, gat_bias + l * 64);

        // global attention (QKV in head-major layout)
        k_gemm<0, true, false, -1, true, false, false><<<dim3(128, 3), 256>>>(
            nullptr, 0, attn_in_w + l * 192 * 64, attn_in_b + l * 192, -1, 8, 192, 64,
            nullptr, nullptr, 0);
        k_attn<<<dim3(32, 4, NSPLIT), 128>>>();
        // out proj with split-merge fused into A-load + residual + BN2 partials
        k_gemm<0, true, true, 2, false, true, false><<<dim3(128, 1), 256>>>(
            nullptr, -1, attn_ow + l * 64 * 64, attn_ob + l * 64, 0, 5, 64, 64,
            nullptr, nullptr, 0);

        // combine (bn1 + bn2) + MLP + norm3
        k_combine<<<64, 256>>>(bn1_g + l * 64, bn1_b + l * 64, bn2_g + l * 64, bn2_b + l * 64);
        k_gemm<2, false, false, -1, false, false, false><<<dim3(128, 2), 256>>>(
            nullptr, 6, mlp_w1 + l * 64 * 128, mlp_b1 + l * 128, -1, 1, 128, 64,
            nullptr, nullptr, 0);
        k_gemm<0, false, true, 3, false, false, false><<<dim3(128, 1), 256>>>(
            nullptr, 1, mlp_w2 + l * 128 * 64, mlp_b2 + l * 64, 6, 7, 64, 128,
            nullptr, nullptr, 0);
        k_bn3relu<<<64, 256>>>(bn3_g + l * 64, bn3_b + l * 64);
    }

    // pooling + classifier
    k_bounds<<<1, 128>>>(batch);
    k_final<<<GG, 64>>>(fin_w, fin_b, (float*)d_out);
}

// round 16
// speedup vs baseline: 2.0785x; 1.4419x over previous
#include <cuda_runtime.h>
#include <math.h>

// ---------------- problem constants (fixed by setup_inputs) ----------------
#define NN 4096       // nodes
#define EE 262144     // edges
#define DD 64         // hidden dim
#define LL 3          // layers
#define HH 4          // attention heads
#define DHH 16        // head dim
#define GG 64         // graphs
#define CC 10         // classes
#define NSPLIT 4      // attention key splits

// ---------------- device global scratch (allowed: no runtime alloc) --------
__device__ float g_X   [NN * DD];
__device__ float g_T128[NN * 128];
__device__ float g_XL  [NN * DD];
__device__ float g_XR  [NN * DD];
__device__ float g_H1R [NN * DD];
__device__ float g_H2R [NN * DD];
__device__ float g_OUT0[NN * DD];
__device__ float g_OUT [NN * DD];
__device__ float g_QKV [3 * HH * NN * DHH];   // head-major: [which][h][n][16]

__device__ int g_cnt   [NN];
__device__ int g_rowptr[NN + 1];
__device__ int g_cursor[NN];
__device__ int g_csrsrc[EE];

// BN partial sums: [block][0..63]=sum, [block][64..127]=sumsq
__device__ float g_part1[512 * 128];   // H1R stats (from k_gat, 512 blocks)
__device__ float g_part2[128 * 128];   // H2R stats (from attn_out gemm, 128 blocks)
__device__ float g_part3[128 * 128];   // OUT stats (from mlp2 gemm, 128 blocks)

// attention split partials: 4 heads x NSPLIT splits
__device__ float g_opart[HH * NSPLIT * NN * DHH];
__device__ float g_mpart[HH * NSPLIT * NN];
__device__ float g_lpart[HH * NSPLIT * NN];

__device__ int g_gbound[GG + 1];

// ---------------- helpers ---------------------------------------------------
// single MUFU.EX2 — exp2f without fast-math is a multi-instruction routine
__device__ __forceinline__ float ex2f(float x) {
    float y;
    asm("ex2.approx.f32 %0, %1;" : "=f"(y) : "f"(x));
    return y;
}

// pack two fp32 to bf16x2: upper = hi-arg, lower = lo-arg
__device__ __forceinline__ unsigned bfpack(float hi, float lo) {
    unsigned d;
    asm("cvt.rn.bf16x2.f32 %0, %1, %2;" : "=r"(d) : "f"(hi), "f"(lo));
    return d;
}

// m16n8k16 row.col bf16 MMA, fp32 accumulate (in place)
__device__ __forceinline__ void mma16816(float& c0, float& c1, float& c2, float& c3,
                                         unsigned a0, unsigned a1, unsigned a2, unsigned a3,
                                         unsigned b0, unsigned b1) {
    asm("mma.sync.aligned.m16n8k16.row.col.f32.bf16.bf16.f32 "
        "{%0,%1,%2,%3}, {%4,%5,%6,%7}, {%8,%9}, {%0,%1,%2,%3};"
        : "+f"(c0), "+f"(c1), "+f"(c2), "+f"(c3)
        : "r"(a0), "r"(a1), "r"(a2), "r"(a3), "r"(b0), "r"(b1));
}

__device__ __forceinline__ float gelu_exact(float v) {
    return 0.5f * v * (1.0f + erff(v * 0.70710678118654752440f));
}

// buffer selector (host cannot take addresses of __device__ globals)
__device__ __forceinline__ float* bufsel(int id) {
    switch (id) {
        case 0: return g_X;
        case 1: return g_T128;
        case 2: return g_XL;
        case 3: return g_XR;
        case 4: return g_H1R;
        case 5: return g_H2R;
        case 6: return g_OUT0;
        case 7: return g_OUT;
        case 8: return g_QKV;
    }
    return nullptr;
}
__device__ __forceinline__ float* partsel(int id) {
    return (id == 2) ? g_part2 : g_part3;
}

// ---------------- CSR build ------------------------------------------------
__global__ void k_zero_cnt() {
    int t = blockIdx.x * blockDim.x + threadIdx.x;
    if (t < NN) g_cnt[t] = 0;
}

__global__ void k_hist(const int* __restrict__ ei) {
    int e = blockIdx.x * blockDim.x + threadIdx.x;
    if (e < EE) atomicAdd(&g_cnt[ei[EE + e]], 1);
}

__global__ void k_scan() {
    __shared__ int sh[1024];
    int t = threadIdx.x;
    int c0 = g_cnt[4 * t], c1 = g_cnt[4 * t + 1], c2 = g_cnt[4 * t + 2], c3 = g_cnt[4 * t + 3];
    int tot = c0 + c1 + c2 + c3;
    sh[t] = tot;
    __syncthreads();
    for (int off = 1; off < 1024; off <<= 1) {
        int v = 0;
        if (t >= off) v = sh[t - off];
        __syncthreads();
        sh[t] += v;
        __syncthreads();
    }
    int excl = sh[t] - tot;
    int p0 = excl, p1 = excl + c0, p2 = p1 + c1, p3 = p2 + c2;
    g_rowptr[4 * t] = p0; g_rowptr[4 * t + 1] = p1;
    g_rowptr[4 * t + 2] = p2; g_rowptr[4 * t + 3] = p3;
    g_cursor[4 * t] = p0; g_cursor[4 * t + 1] = p1;
    g_cursor[4 * t + 2] = p2; g_cursor[4 * t + 3] = p3;
    if (t == 1023) g_rowptr[NN] = p3 + c3;
}

__global__ void k_scatter(const int* __restrict__ ei) {
    int e = blockIdx.x * blockDim.x + threadIdx.x;
    if (e < EE) {
        int d = ei[EE + e];
        int pos = atomicAdd(&g_cursor[d], 1);
        g_csrsrc[pos] = ei[e];
    }
}

// ---------------- generic small SGEMM (4096 rows) ---------------------------
// C[row, n0+col] = act( sum_k A[row,k]*B(k,col) + bias[col] (+ res[row,col]) )
// ACT: 0 none, 1 gelu, 2 relu.  TB: B given as [Ntot, K] (use B^T).
// STATS >= 0: emit per-block column sum/sumsq partials (y==1, Ntot==64).
// QKVOUT: store to head-major g_QKV layout.
// MERGEA: A tile = attention split-merge of this block's rows (K==64).
// DUAL: blockIdx.y selects (B,bias,out) vs (B2,bias2,out2); n0=0.
template <int ACT, bool TB, bool RES, int STATS, bool QKVOUT, bool MERGEA, bool DUAL>
__global__ void __launch_bounds__(256) k_gemm(const float* __restrict__ Aext, int aSel,
                                              const float* __restrict__ B,
                                              const float* __restrict__ bias,
                                              int resSel, int cSel, int Ntot, int K,
                                              const float* __restrict__ B2,
                                              const float* __restrict__ bias2,
                                              int cSel2) {
    __shared__ float As[32 * 128];
    __shared__ float Bs[128 * 64];
    const float* A = (aSel >= 0) ? bufsel(aSel) : Aext;
    float* Cm;
    if (DUAL) {
        if (blockIdx.y == 1) { B = B2; bias = bias2; Cm = bufsel(cSel2); }
        else                 { Cm = bufsel(cSel); }
    } else {
        Cm = bufsel(cSel);
    }
    const float* res = RES ? bufsel(resSel) : nullptr;

    int rb = blockIdx.x * 32;
    int n0 = DUAL ? 0 : blockIdx.y * 64;
    int tid = threadIdx.x;

    if (MERGEA) {
        // A tile = merged attention output for rows rb..rb+31 (K == 64)
        if (tid < 128) {
            int r = tid >> 2, h = tid & 3, q = rb + r;
            float mv[NSPLIT], mb = -1e30f;
#pragma unroll
            for (int sp = 0; sp < NSPLIT; sp++) {
                mv[sp] = g_mpart[(h * NSPLIT + sp) * NN + q];
                mb = fmaxf(mb, mv[sp]);
            }
            float L = 0.f, o[16] = {};
#pragma unroll
            for (int sp = 0; sp < NSPLIT; sp++) {
                float w = ex2f(mv[sp] - mb);
                int pidx = (h * NSPLIT + sp) * NN + q;
                L += g_lpart[pidx] * w;
                const float4* op4 = (const float4*)(g_opart + pidx * 16);
#pragma unroll
                for (int i = 0; i < 4; i++) {
                    float4 vv = op4[i];
                    o[4 * i + 0] = fmaf(vv.x, w, o[4 * i + 0]);
                    o[4 * i + 1] = fmaf(vv.y, w, o[4 * i + 1]);
                    o[4 * i + 2] = fmaf(vv.z, w, o[4 * i + 2]);
                    o[4 * i + 3] = fmaf(vv.w, w, o[4 * i + 3]);
                }
            }
            float inv = 1.0f / L;
#pragma unroll
            for (int d = 0; d < 16; d++) As[r * 64 + h * 16 + d] = o[d] * inv;
        }
    } else {
        for (int idx = tid; idx < 32 * K; idx += 256) As[idx] = A[rb * K + idx];
    }
    for (int idx = tid; idx < K * 64; idx += 256) {
        if (TB) {
            int n = idx / K;
            int k = idx - n * K;
            Bs[k * 64 + n] = B[(n0 + n) * K + k];
        } else {
            int k = idx >> 6;
            int n = idx & 63;
            Bs[k * 64 + n] = B[k * Ntot + n0 + n];
        }
    }
    __syncthreads();

    int tr = tid >> 4;       // 0..15 (rows tr, tr+16)
    int tc = tid & 15;       // 0..15 (cols tc*4..tc*4+3)
    float acc[2][4] = {};
    for (int k = 0; k < K; k++) {
        float a0 = As[tr * K + k];
        float a1 = As[(tr + 16) * K + k];
        float4 b = *(const float4*)&Bs[k * 64 + tc * 4];
        acc[0][0] = fmaf(a0, b.x, acc[0][0]);
        acc[0][1] = fmaf(a0, b.y, acc[0][1]);
        acc[0][2] = fmaf(a0, b.z, acc[0][2]);
        acc[0][3] = fmaf(a0, b.w, acc[0][3]);
        acc[1][0] = fmaf(a1, b.x, acc[1][0]);
        acc[1][1] = fmaf(a1, b.y, acc[1][1]);
        acc[1][2] = fmaf(a1, b.z, acc[1][2]);
        acc[1][3] = fmaf(a1, b.w, acc[1][3]);
    }
    float sl[4] = {}, ql[4] = {};
#pragma unroll
    for (int r = 0; r < 2; r++) {
        int row = rb + tr + r * 16;
#pragma unroll
        for (int i = 0; i < 4; i++) {
            int col = n0 + tc * 4 + i;
            float v = acc[r][i] + bias[col];
            if (RES) v += res[row * Ntot + col];
            if (ACT == 1) v = gelu_exact(v);
            if (ACT == 2) v = fmaxf(v, 0.0f);
            if (QKVOUT) {
                int which = col >> 6, hh = (col >> 4) & 3, d = col & 15;
                g_QKV[which * (HH * NN * DHH) + (hh * NN + row) * DHH + d] = v;
            } else {
                Cm[row * Ntot + col] = v;
            }
            if (STATS >= 0) { sl[i] += v; ql[i] = fmaf(v, v, ql[i]); }
        }
    }
    if (STATS >= 0) {
        __syncthreads();   // done with As main-loop reads
#pragma unroll
        for (int i = 0; i < 4; i++) {
            As[tr * 128 + tc * 4 + i]      = sl[i];
            As[tr * 128 + 64 + tc * 4 + i] = ql[i];
        }
        __syncthreads();
        if (tid < 128) {
            float S = 0.f;
#pragma unroll
            for (int r = 0; r < 16; r++) S += As[r * 128 + tid];
            partsel(STATS)[blockIdx.x * 128 + tid] = S;
        }
    }
}

// ---------------- GATv2: fused one-pass, 4 edge-groups x 8 lanes -----------
// warp = one dst node; lanes split into 4 groups of 8; each group runs an
// independent online softmax over every 4th edge; groups merged via shfl.
// Edge loop software-prefetches the next source row to hide L2 latency.
__global__ void __launch_bounds__(256) k_gat(const float* __restrict__ att,
                                             const float* __restrict__ gbias) {
    const float L2E = 1.4426950408889634f;
    int warp = threadIdx.x >> 5, lane = threadIdx.x & 31;
    int grp = lane >> 3;
    unsigned gm = 0xFFu << (grp * 8);   // group-local shuffle mask
    int fb = (lane & 7) * 8;            // feature block [fb, fb+8)
    int v = blockIdx.x * 8 + warp;

    float4 xra = *(const float4*)&g_XR[v * 64 + fb];
    float4 xrb = *(const float4*)&g_XR[v * 64 + fb + 4];
    float4 ata = *(const float4*)&att[fb];
    float4 atb = *(const float4*)&att[fb + 4];
    ata.x *= L2E; ata.y *= L2E; ata.z *= L2E; ata.w *= L2E;
    atb.x *= L2E; atb.y *= L2E; atb.z *= L2E; atb.w *= L2E;

#define GAT_SCORE(E, XA, XB)                                                  \
    {                                                                         \
        float z, p = 0.f;                                                     \
        z = XA.x + xra.x; z = fmaxf(z, 0.2f * z); p = fmaf(z, ata.x, p);      \
        z = XA.y + xra.y; z = fmaxf(z, 0.2f * z); p = fmaf(z, ata.y, p);      \
        z = XA.z + xra.z; z = fmaxf(z, 0.2f * z); p = fmaf(z, ata.z, p);      \
        z = XA.w + xra.w; z = fmaxf(z, 0.2f * z); p = fmaf(z, ata.w, p);      \
        z = XB.x + xrb.x; z = fmaxf(z, 0.2f * z); p = fmaf(z, atb.x, p);      \
        z = XB.y + xrb.y; z = fmaxf(z, 0.2f * z); p = fmaf(z, atb.y, p);      \
        z = XB.z + xrb.z; z = fmaxf(z, 0.2f * z); p = fmaf(z, atb.z, p);      \
        z = XB.w + xrb.w; z = fmaxf(z, 0.2f * z); p = fmaf(z, atb.w, p);      \
        p += __shfl_xor_sync(gm, p, 1);                                       \
        p += __shfl_xor_sync(gm, p, 2);                                       \
        p += __shfl_xor_sync(gm, p, 4);                                       \
        E = p;                                                                \
    }

    // self-loop seeds group 0; other groups start empty (m=-inf, l=0, acc=0)
    float4 xa = *(const float4*)&g_XL[v * 64 + fb];
    float4 xb = *(const float4*)&g_XL[v * 64 + fb + 4];
    float e;
    GAT_SCORE(e, xa, xb);
    bool g0 = (grp == 0);
    float m = g0 ? e : -1e30f;
    float l = g0 ? 1.f : 0.f;
    float4 aca, acb;
    aca.x = g0 ? xa.x : 0.f; aca.y = g0 ? xa.y : 0.f;
    aca.z = g0 ? xa.z : 0.f; aca.w = g0 ? xa.w : 0.f;
    acb.x = g0 ? xb.x : 0.f; acb.y = g0 ? xb.y : 0.f;
    acb.z = g0 ? xb.z : 0.f; acb.w = g0 ? xb.w : 0.f;

    int beg = g_rowptr[v], end = g_rowptr[v + 1];
    int k = beg + grp;
    if (k < end) {
        int s = g_csrsrc[k];
        float4 nxa = *(const float4*)&g_XL[s * 64 + fb];
        float4 nxb = *(const float4*)&g_XL[s * 64 + fb + 4];
        while (true) {
            xa = nxa; xb = nxb;
            int kn = k + 4;
            if (kn < end) {      // group-uniform branch
                int sn = g_csrsrc[kn];
                nxa = *(const float4*)&g_XL[sn * 64 + fb];
                nxb = *(const float4*)&g_XL[sn * 64 + fb + 4];
            }
            GAT_SCORE(e, xa, xb);
            float nm = fmaxf(m, e);
            float sc = ex2f(m - nm);
            float w  = ex2f(e - nm);
            l = fmaf(l, sc, w);
            aca.x = fmaf(aca.x, sc, w * xa.x);
            aca.y = fmaf(aca.y, sc, w * xa.y);
            aca.z = fmaf(aca.z, sc, w * xa.z);
            aca.w = fmaf(aca.w, sc, w * xa.w);
            acb.x = fmaf(acb.x, sc, w * xb.x);
            acb.y = fmaf(acb.y, sc, w * xb.y);
            acb.z = fmaf(acb.z, sc, w * xb.z);
            acb.w = fmaf(acb.w, sc, w * xb.w);
            m = nm;
            k = kn;
            if (k >= end) break;
        }
    }
    __syncwarp();   // reconverge all 32 lanes before cross-group merge

    // merge the 4 groups (lanes g, g+8, g+16, g+24 share a feature block)
    float mo = fmaxf(m, __shfl_xor_sync(0xffffffffu, m, 8));
    mo = fmaxf(mo, __shfl_xor_sync(0xffffffffu, mo, 16));
    float wq = ex2f(m - mo);
    l *= wq;
    l += __shfl_xor_sync(0xffffffffu, l, 8);
    l += __shfl_xor_sync(0xffffffffu, l, 16);
#define GAT_MRG(R)                                    \
    R *= wq;                                          \
    R += __shfl_xor_sync(0xffffffffu, R, 8);          \
    R += __shfl_xor_sync(0xffffffffu, R, 16);
    GAT_MRG(aca.x) GAT_MRG(aca.y) GAT_MRG(aca.z) GAT_MRG(aca.w)
    GAT_MRG(acb.x) GAT_MRG(acb.y) GAT_MRG(acb.z) GAT_MRG(acb.w)
    float inv = 1.0f / l;

    __shared__ float shs[512], shq[512];
    if (g0) {
        float4 bia = *(const float4*)&gbias[fb];
        float4 bib = *(const float4*)&gbias[fb + 4];
        float4 rxa = *(const float4*)&g_X[v * 64 + fb];
        float4 rxb = *(const float4*)&g_X[v * 64 + fb + 4];
        float4 oa, ob;
        oa.x = fmaf(aca.x, inv, bia.x + rxa.x);
        oa.y = fmaf(aca.y, inv, bia.y + rxa.y);
        oa.z = fmaf(aca.z, inv, bia.z + rxa.z);
        oa.w = fmaf(aca.w, inv, bia.w + rxa.w);
        ob.x = fmaf(acb.x, inv, bib.x + rxb.x);
        ob.y = fmaf(acb.y, inv, bib.y + rxb.y);
        ob.z = fmaf(acb.z, inv, bib.z + rxb.z);
        ob.w = fmaf(acb.w, inv, bib.w + rxb.w);
        *(float4*)&g_H1R[v * 64 + fb]     = oa;
        *(float4*)&g_H1R[v * 64 + fb + 4] = ob;
        float4 qa, qb;
        qa.x = oa.x * oa.x; qa.y = oa.y * oa.y; qa.z = oa.z * oa.z; qa.w = oa.w * oa.w;
        qb.x = ob.x * ob.x; qb.y = ob.y * ob.y; qb.z = ob.z * ob.z; qb.w = ob.w * ob.w;
        *(float4*)&shs[warp * 64 + fb]     = oa;
        *(float4*)&shs[warp * 64 + fb + 4] = ob;
        *(float4*)&shq[warp * 64 + fb]     = qa;
        *(float4*)&shq[warp * 64 + fb + 4] = qb;
    }
    __syncthreads();
    int t = threadIdx.x;
    if (t < 64) {
        float S = 0.f, Q = 0.f;
#pragma unroll
        for (int w = 0; w < 8; w++) { S += shs[w * 64 + t]; Q += shq[w * 64 + t]; }
        g_part1[blockIdx.x * 128 + t]      = S;
        g_part1[blockIdx.x * 128 + 64 + t] = Q;
    }
}

// ---------------- BatchNorm reduce (from per-block partials) ---------------
template <int NB>
__device__ void stats_reduceN(const float* part, float* mu, float* istd, float* scr) {
    int t = threadIdx.x;
    int f = t & 63, c = t >> 6;
    float s = 0.f, q = 0.f;
    for (int b = c; b < NB; b += 4) {
        s += part[b * 128 + f];
        q += part[b * 128 + 64 + f];
    }
    scr[t] = s; scr[256 + t] = q;
    __syncthreads();
    if (t < 64) {
        float S = scr[t] + scr[t + 64] + scr[t + 128] + scr[t + 192];
        float Q = scr[256 + t] + scr[256 + t + 64] + scr[256 + t + 128] + scr[256 + t + 192];
        float m = S * (1.0f / NN);
        mu[t] = m;
        istd[t] = rsqrtf(Q * (1.0f / NN) - m * m + 1e-5f);
    }
    __syncthreads();
}

// OUT0 = bn1(H1R) + bn2(H2R)
__global__ void __launch_bounds__(256) k_combine(const float* __restrict__ g1, const float* __restrict__ b1,
                                                 const float* __restrict__ g2, const float* __restrict__ b2) {
    __shared__ float scr[512];
    __shared__ float mu1[64], is1[64], mu2[64], is2[64];
    stats_reduceN<512>(g_part1, mu1, is1, scr);
    stats_reduceN<128>(g_part2, mu2, is2, scr);
    int t = threadIdx.x;
    int base = blockIdx.x * 4096;
#pragma unroll
    for (int i = 0; i < 16; i++) {
        int o = base + t + i * 256;
        int f = o & 63;
        float v1 = (g_H1R[o] - mu1[f]) * is1[f] * g1[f] + b1[f];
        float v2 = (g_H2R[o] - mu2[f]) * is2[f] * g2[f] + b2[f];
        g_OUT0[o] = v1 + v2;
    }
}

// X = relu(bn3(OUT))
__global__ void __launch_bounds__(256) k_bn3relu(const float* __restrict__ g3, const float* __restrict__ b3) {
    __shared__ float scr[512];
    __shared__ float mu[64], is[64];
    stats_reduceN<128>(g_part3, mu, is, scr);
    int t = threadIdx.x;
    int base = blockIdx.x * 4096;
#pragma unroll
    for (int i = 0; i < 16; i++) {
        int o = base + t + i * 256;
        int f = o & 63;
        float v = (g_OUT[o] - mu[f]) * is[f] * g3[f] + b3[f];
        g_X[o] = fmaxf(v, 0.0f);
    }
}

// ---------------- global attention (flash, bf16-split HMMA) -----------------
// grid (64 q-tiles of 64, 4 heads, NSPLIT key-splits), 128 threads (4 warps,
// 16 queries/warp). K staged [key][18] bf16 hi/lo; V staged transposed
// [dim][264] bf16 hi/lo. Softmax in fp32 on MMA C-fragments.
#define KPAD 18
#define VPAD 264
__global__ void __launch_bounds__(128) k_attn() {
    __shared__ __align__(16) unsigned short sKh[256 * KPAD];
    __shared__ __align__(16) unsigned short sKl[256 * KPAD];
    __shared__ __align__(16) unsigned short sVh[16 * VPAD];
    __shared__ __align__(16) unsigned short sVl[16 * VPAD];

    int tid = threadIdx.x;
    int w = tid >> 5, lane = tid & 31;
    int gid = lane >> 2, t4 = lane & 3;
    int h = blockIdx.y, sp = blockIdx.z;
    int q0 = blockIdx.x * 64 + w * 16;
    const float cs = 0.25f * 1.4426950408889634f;   // (1/sqrt(dh)) * log2(e)

    const float* QB = g_QKV;
    const float* KB = g_QKV + HH * NN * DHH;
    const float* VB = g_QKV + 2 * HH * NN * DHH;

    // Q fragments (hi/lo bf16 split), scores in log2 domain
    unsigned qh[4], ql[4];
    {
        const float* r0p = QB + (h * NN + q0 + gid) * 16;
#pragma unroll
        for (int i = 0; i < 4; i++) {
            const float* rp = r0p + ((i & 1) ? 8 * 16 : 0);
            int d = ((i >> 1) ? 8 : 0) + t4 * 2;
            float x0 = rp[d] * cs, x1 = rp[d + 1] * cs;
            unsigned hh = bfpack(x1, x0);
            float h0 = __uint_as_float(hh << 16);
            float h1 = __uint_as_float(hh & 0xffff0000u);
            qh[i] = hh;
            ql[i] = bfpack(x1 - h1, x0 - h0);
        }
    }

    float o[8] = {};                     // O: [dim-half][c0..c3]
    float m0 = -1e30f, m1 = -1e30f, l0 = 0.f, l1 = 0.f;

    for (int ch = 0; ch < (NN / NSPLIT) / 256; ch++) {
        int base = sp * (NN / NSPLIT) + ch * 256;
        __syncthreads();
        // stage K: [256 keys][16 dims] -> bf16 hi/lo, padded rows
        const float4* kg = (const float4*)(KB + (h * NN + base) * 16);
        for (int i = tid; i < 1024; i += 128) {
            float4 v = kg[i];
            int key = i >> 2, dq = (i & 3) * 4;
            unsigned h01 = bfpack(v.y, v.x);
            float f0 = __uint_as_float(h01 << 16), f1 = __uint_as_float(h01 & 0xffff0000u);
            unsigned l01 = bfpack(v.y - f1, v.x - f0);
            unsigned h23 = bfpack(v.w, v.z);
            float f2 = __uint_as_float(h23 << 16), f3 = __uint_as_float(h23 & 0xffff0000u);
            unsigned l23 = bfpack(v.w - f3, v.z - f2);
            int off = key * KPAD + dq;
            *(unsigned*)&sKh[off] = h01; *(unsigned*)&sKh[off + 2] = h23;
            *(unsigned*)&sKl[off] = l01; *(unsigned*)&sKl[off + 2] = l23;
        }
        // stage V transposed: [16 dims][256 keys] bf16 hi/lo
        const float* vg = VB + (h * NN + base) * 16;
        for (int i = tid; i < 4096; i += 128) {
            float x = vg[i];
            int key = i >> 4, d = i & 15;
            unsigned hb = bfpack(0.f, x) & 0xffffu;
            float hf = __uint_as_float(hb << 16);
            unsigned lb = bfpack(0.f, x - hf) & 0xffffu;
            sVh[d * VPAD + key] = (unsigned short)hb;
            sVl[d * VPAD + key] = (unsigned short)lb;
        }
        __syncthreads();

        for (int g = 0; g < 16; g++) {
            int kb = g * 16;
            float c[8] = {};             // two 16x8 S tiles
#pragma unroll
            for (int t = 0; t < 2; t++) {
                int krow = (kb + t * 8 + gid) * KPAD;
                unsigned b0h = *(const unsigned*)&sKh[krow + t4 * 2];
                unsigned b1h = *(const unsigned*)&sKh[krow + 8 + t4 * 2];
                unsigned b0l = *(const unsigned*)&sKl[krow + t4 * 2];
                unsigned b1l = *(const unsigned*)&sKl[krow + 8 + t4 * 2];
                float* ct = c + t * 4;
                mma16816(ct[0], ct[1], ct[2], ct[3], qh[0], qh[1], qh[2], qh[3], b0h, b1h);
                mma16816(ct[0], ct[1], ct[2], ct[3], qh[0], qh[1], qh[2], qh[3], b0l, b1l);
                mma16816(ct[0], ct[1], ct[2], ct[3], ql[0], ql[1], ql[2], ql[3], b0h, b1h);
            }
            // online softmax (log2 domain)
            float s0 = fmaxf(fmaxf(c[0], c[1]), fmaxf(c[4], c[5]));
            float s1 = fmaxf(fmaxf(c[2], c[3]), fmaxf(c[6], c[7]));
            s0 = fmaxf(s0, __shfl_xor_sync(0xffffffffu, s0, 1));
            s0 = fmaxf(s0, __shfl_xor_sync(0xffffffffu, s0, 2));
            s1 = fmaxf(s1, __shfl_xor_sync(0xffffffffu, s1, 1));
            s1 = fmaxf(s1, __shfl_xor_sync(0xffffffffu, s1, 2));
            float nm0 = fmaxf(m0, s0), nm1 = fmaxf(m1, s1);
            float sc0 = ex2f(m0 - nm0), sc1 = ex2f(m1 - nm1);
            m0 = nm0; m1 = nm1;
            l0 *= sc0; l1 *= sc1;
            o[0] *= sc0; o[1] *= sc0; o[2] *= sc1; o[3] *= sc1;
            o[4] *= sc0; o[5] *= sc0; o[6] *= sc1; o[7] *= sc1;
            float p0 = ex2f(c[0] - m0), p1 = ex2f(c[1] - m0);
            float p2 = ex2f(c[2] - m1), p3 = ex2f(c[3] - m1);
            float p4 = ex2f(c[4] - m0), p5 = ex2f(c[5] - m0);
            float p6 = ex2f(c[6] - m1), p7 = ex2f(c[7] - m1);
            l0 += (p0 + p1) + (p4 + p5);
            l1 += (p2 + p3) + (p6 + p7);
            unsigned a0 = bfpack(p1, p0);   // P row gid,   keys kb+t4*2..+1
            unsigned a1 = bfpack(p3, p2);   // P row gid+8, keys kb+t4*2..+1
            unsigned a2 = bfpack(p5, p4);   // P row gid,   keys kb+8+t4*2..+1
            unsigned a3 = bfpack(p7, p6);   // P row gid+8, keys kb+8+t4*2..+1
#pragma unroll
            for (int nh = 0; nh < 2; nh++) {
                int vrow = (nh * 8 + gid) * VPAD + kb;
                unsigned vb0h = *(const unsigned*)&sVh[vrow + t4 * 2];
                unsigned vb1h = *(const unsigned*)&sVh[vrow + 8 + t4 * 2];
                unsigned vb0l = *(const unsigned*)&sVl[vrow + t4 * 2];
                unsigned vb1l = *(const unsigned*)&sVl[vrow + 8 + t4 * 2];
                float* ot = o + nh * 4;
                mma16816(ot[0], ot[1], ot[2], ot[3], a0, a1, a2, a3, vb0h, vb1h);
                mma16816(ot[0], ot[1], ot[2], ot[3], a0, a1, a2, a3, vb0l, vb1l);
            }
        }
    }
    // finalize: quad-reduce l, write partials (same format as before)
    l0 += __shfl_xor_sync(0xffffffffu, l0, 1);
    l0 += __shfl_xor_sync(0xffffffffu, l0, 2);
    l1 += __shfl_xor_sync(0xffffffffu, l1, 1);
    l1 += __shfl_xor_sync(0xffffffffu, l1, 2);
    int r0 = q0 + gid, r1 = r0 + 8;
    int pidx0 = (h * NSPLIT + sp) * NN + r0;
    int pidx1 = (h * NSPLIT + sp) * NN + r1;
    float* op0 = g_opart + pidx0 * 16;
    float* op1 = g_opart + pidx1 * 16;
    op0[t4 * 2]         = o[0]; op0[t4 * 2 + 1]     = o[1];
    op0[8 + t4 * 2]     = o[4]; op0[8 + t4 * 2 + 1] = o[5];
    op1[t4 * 2]         = o[2]; op1[t4 * 2 + 1]     = o[3];
    op1[8 + t4 * 2]     = o[6]; op1[8 + t4 * 2 + 1] = o[7];
    if (t4 == 0) {
        g_mpart[pidx0] = m0; g_lpart[pidx0] = l0;
        g_mpart[pidx1] = m1; g_lpart[pidx1] = l1;
    }
}

// ---------------- pooling + classifier -------------------------------------
__global__ void k_bounds(const int* __restrict__ batch) {
    int t = threadIdx.x;
    if (t <= GG) {
        int lo = 0, hi = NN;
        while (lo < hi) {
            int mid = (lo + hi) >> 1;
            if (batch[mid] < t) lo = mid + 1; else hi = mid;
        }
        g_gbound[t] = lo;
    }
}

__global__ void __launch_bounds__(64) k_final(const float* __restrict__ fin_w,
                                              const float* __restrict__ fin_b,
                                              float* __restrict__ out) {
    int g = blockIdx.x, t = threadIdx.x;
    int s0 = g_gbound[g], s1 = g_gbound[g + 1];
    int cnt = s1 - s0;
    float s = 0.f;
    for (int r = s0; r < s1; r++) s += g_X[r * 64 + t];
    __shared__ float mean[64];
    __shared__ float lg[CC];
    __shared__ float lse;
    mean[t] = s / (float)max(cnt, 1);
    __syncthreads();
    if (t < CC) {
        float a = fin_b[t];
        for (int f = 0; f < 64; f++) a = fmaf(mean[f], fin_w[f * CC + t], a);
        lg[t] = a;
    }
    __syncthreads();
    if (t == 0) {
        float mx = lg[0];
        for (int c = 1; c < CC; c++) mx = fmaxf(mx, lg[c]);
        float se = 0.f;
        for (int c = 0; c < CC; c++) se += expf(lg[c] - mx);
        lse = mx + logf(se);
    }
    __syncthreads();
    if (t < CC) out[g * CC + t] = lg[t] - lse;
}

// ---------------- launch ----------------------------------------------------
extern "C" void kernel_launch(void* const* d_in, const int* in_sizes, int n_in,
                              void* d_out, int out_size) {
    const float* x         = (const float*)d_in[0];
    const int*   ei        = (const int*)d_in[1];
    const int*   batch     = (const int*)d_in[2];
    const float* pre_w1    = (const float*)d_in[3];
    const float* pre_b1    = (const float*)d_in[4];
    const float* pre_w2    = (const float*)d_in[5];
    const float* pre_b2    = (const float*)d_in[6];
    const float* gat_wl    = (const float*)d_in[7];
    const float* gat_bl    = (const float*)d_in[8];
    const float* gat_wr    = (const float*)d_in[9];
    const float* gat_br    = (const float*)d_in[10];
    const float* gat_att   = (const float*)d_in[11];
    const float* gat_bias  = (const float*)d_in[12];
    const float* attn_in_w = (const float*)d_in[13];
    const float* attn_in_b = (const float*)d_in[14];
    const float* attn_ow   = (const float*)d_in[15];
    const float* attn_ob   = (const float*)d_in[16];
    const float* bn1_g     = (const float*)d_in[17];
    const float* bn1_b     = (const float*)d_in[18];
    const float* bn2_g     = (const float*)d_in[19];
    const float* bn2_b     = (const float*)d_in[20];
    const float* bn3_g     = (const float*)d_in[21];
    const float* bn3_b     = (const float*)d_in[22];
    const float* mlp_w1    = (const float*)d_in[23];
    const float* mlp_b1    = (const float*)d_in[24];
    const float* mlp_w2    = (const float*)d_in[25];
    const float* mlp_b2    = (const float*)d_in[26];
    const float* fin_w     = (const float*)d_in[27];
    const float* fin_b     = (const float*)d_in[28];

    // CSR of incoming edges (same every layer)
    k_zero_cnt<<<16, 256>>>();
    k_hist<<<EE / 256, 256>>>(ei);
    k_scan<<<1, 1024>>>();
    k_scatter<<<EE / 256, 256>>>(ei);

    // preprocess MLP
    k_gemm<1, false, false, -1, false, false, false><<<dim3(128, 2), 256>>>(
        x, -1, pre_w1, pre_b1, -1, 1, 128, 9, nullptr, nullptr, 0);
    k_gemm<1, false, false, -1, false, false, false><<<dim3(128, 1), 256>>>(
        nullptr, 1, pre_w2, pre_b2, -1, 0, 64, 128, nullptr, nullptr, 0);

    for (int l = 0; l < LL; l++) {
        // local GATv2: xl+xr in ONE dual launch, then fused one-pass GAT
        k_gemm<0, false, false, -1, false, false, true><<<dim3(128, 2), 256>>>(
            nullptr, 0, gat_wl + l * 64 * 64, gat_bl + l * 64, -1, 2, 64, 64,
            gat_wr + l * 64 * 64, gat_br + l * 64, 3);
        k_gat<<<512, 256>>>(gat_att + l * 64, gat_bias + l * 64);

        // global attention (QKV in head-major layout) — HMMA bf16-split flash
        k_gemm<0, true, false, -1, true, false, false><<<dim3(128, 3), 256>>>(
            nullptr, 0, attn_in_w + l * 192 * 64, attn_in_b + l * 192, -1, 8, 192, 64,
            nullptr, nullptr, 0);
        k_attn<<<dim3(64, 4, NSPLIT), 128>>>();
        // out proj with split-merge fused into A-load + residual + BN2 partials
        k_gemm<0, true, true, 2, false, true, false><<<dim3(128, 1), 256>>>(
            nullptr, -1, attn_ow + l * 64 * 64, attn_ob + l * 64, 0, 5, 64, 64,
            nullptr, nullptr, 0);

        // combine (bn1 + bn2) + MLP + norm3
        k_combine<<<64, 256>>>(bn1_g + l * 64, bn1_b + l * 64, bn2_g + l * 64, bn2_b + l * 64);
        k_gemm<2, false, false, -1, false, false, false><<<dim3(128, 2), 256>>>(
            nullptr, 6, mlp_w1 + l * 64 * 128, mlp_b1 + l * 128, -1, 1, 128, 64,
            nullptr, nullptr, 0);
        k_gemm<0, false, true, 3, false, false, false><<<dim3(128, 1), 256>>>(
            nullptr, 1, mlp_w2 + l * 128 * 64, mlp_b2 + l * 64, 6, 7, 64, 128,
            nullptr, nullptr, 0);
        k_bn3relu<<<64, 256>>>(bn3_g + l * 64, bn3_b + l * 64);
    }

    // pooling + classifier
    k_bounds<<<1, 128>>>(batch);
    k_final<<<GG, 64>>>(fin_w, fin_b, (float*)d_out);
}

// round 17
// speedup vs baseline: 2.2597x; 1.0872x over previous
#include <cuda_runtime.h>
#include <math.h>

// ---------------- problem constants (fixed by setup_inputs) ----------------
#define NN 4096       // nodes
#define EE 262144     // edges
#define DD 64         // hidden dim
#define LL 3          // layers
#define HH 4          // attention heads
#define DHH 16        // head dim
#define GG 64         // graphs
#define CC 10         // classes
#define NSPLIT 4      // attention key splits
#define KPAD 18
#define VPAD 264

// ---------------- device global scratch (allowed: no runtime alloc) --------
__device__ float g_X   [NN * DD];
__device__ float g_T128[NN * 128];
__device__ float g_XL  [NN * DD];
__device__ float g_XR  [NN * DD];
__device__ float g_H1R [NN * DD];
__device__ float g_H2R [NN * DD];
__device__ float g_OUT0[NN * DD];
__device__ float g_OUT [NN * DD];
__device__ float g_Q   [HH * NN * DHH];            // fp32 Q, head-major
__device__ unsigned short g_K18h[HH * NN * KPAD];  // bf16-hi K, padded rows
__device__ unsigned short g_K18l[HH * NN * KPAD];  // bf16-lo K
__device__ unsigned short g_Vth [HH * DHH * NN];   // bf16-hi V, transposed
__device__ unsigned short g_Vtl [HH * DHH * NN];   // bf16-lo V

__device__ int g_cnt   [NN];
__device__ int g_rowptr[NN + 1];
__device__ int g_cursor[NN];
__device__ int g_csrsrc[EE];

// BN partial sums: [block][0..63]=sum, [block][64..127]=sumsq
__device__ float g_part1[512 * 128];   // H1R stats (from k_gat, 512 blocks)
__device__ float g_part2[128 * 128];   // H2R stats (from attn_out gemm, 128 blocks)
__device__ float g_part3[128 * 128];   // OUT stats (from mlp2 gemm, 128 blocks)

// attention split partials: 4 heads x NSPLIT splits
__device__ float g_opart[HH * NSPLIT * NN * DHH];
__device__ float g_mpart[HH * NSPLIT * NN];
__device__ float g_lpart[HH * NSPLIT * NN];

__device__ int g_gbound[GG + 1];

// ---------------- helpers ---------------------------------------------------
__device__ __forceinline__ float ex2f(float x) {
    float y;
    asm("ex2.approx.f32 %0, %1;" : "=f"(y) : "f"(x));
    return y;
}

// pack two fp32 to bf16x2: upper = hi-arg, lower = lo-arg
__device__ __forceinline__ unsigned bfpack(float hi, float lo) {
    unsigned d;
    asm("cvt.rn.bf16x2.f32 %0, %1, %2;" : "=r"(d) : "f"(hi), "f"(lo));
    return d;
}

// m16n8k16 row.col bf16 MMA, fp32 accumulate (in place)
__device__ __forceinline__ void mma16816(float& c0, float& c1, float& c2, float& c3,
                                         unsigned a0, unsigned a1, unsigned a2, unsigned a3,
                                         unsigned b0, unsigned b1) {
    asm("mma.sync.aligned.m16n8k16.row.col.f32.bf16.bf16.f32 "
        "{%0,%1,%2,%3}, {%4,%5,%6,%7}, {%8,%9}, {%0,%1,%2,%3};"
        : "+f"(c0), "+f"(c1), "+f"(c2), "+f"(c3)
        : "r"(a0), "r"(a1), "r"(a2), "r"(a3), "r"(b0), "r"(b1));
}

__device__ __forceinline__ float gelu_exact(float v) {
    return 0.5f * v * (1.0f + erff(v * 0.70710678118654752440f));
}

// buffer selector (host cannot take addresses of __device__ globals)
__device__ __forceinline__ float* bufsel(int id) {
    switch (id) {
        case 0: return g_X;
        case 1: return g_T128;
        case 2: return g_XL;
        case 3: return g_XR;
        case 4: return g_H1R;
        case 5: return g_H2R;
        case 6: return g_OUT0;
        case 7: return g_OUT;
    }
    return nullptr;
}
__device__ __forceinline__ float* partsel(int id) {
    return (id == 2) ? g_part2 : g_part3;
}

// ---------------- CSR build ------------------------------------------------
__global__ void k_zero_cnt() {
    int t = blockIdx.x * blockDim.x + threadIdx.x;
    if (t < NN) g_cnt[t] = 0;
}

__global__ void k_hist(const int* __restrict__ ei) {
    int e = blockIdx.x * blockDim.x + threadIdx.x;
    if (e < EE) atomicAdd(&g_cnt[ei[EE + e]], 1);
}

__global__ void k_scan() {
    __shared__ int sh[1024];
    int t = threadIdx.x;
    int c0 = g_cnt[4 * t], c1 = g_cnt[4 * t + 1], c2 = g_cnt[4 * t + 2], c3 = g_cnt[4 * t + 3];
    int tot = c0 + c1 + c2 + c3;
    sh[t] = tot;
    __syncthreads();
    for (int off = 1; off < 1024; off <<= 1) {
        int v = 0;
        if (t >= off) v = sh[t - off];
        __syncthreads();
        sh[t] += v;
        __syncthreads();
    }
    int excl = sh[t] - tot;
    int p0 = excl, p1 = excl + c0, p2 = p1 + c1, p3 = p2 + c2;
    g_rowptr[4 * t] = p0; g_rowptr[4 * t + 1] = p1;
    g_rowptr[4 * t + 2] = p2; g_rowptr[4 * t + 3] = p3;
    g_cursor[4 * t] = p0; g_cursor[4 * t + 1] = p1;
    g_cursor[4 * t + 2] = p2; g_cursor[4 * t + 3] = p3;
    if (t == 1023) g_rowptr[NN] = p3 + c3;
}

__global__ void k_scatter(const int* __restrict__ ei) {
    int e = blockIdx.x * blockDim.x + threadIdx.x;
    if (e < EE) {
        int d = ei[EE + e];
        int pos = atomicAdd(&g_cursor[d], 1);
        g_csrsrc[pos] = ei[e];
    }
}

// ---------------- generic small SGEMM (4096 rows) ---------------------------
// C[row, n0+col] = act( sum_k A[row,k]*B(k,col) + bias[col] (+ res[row,col]) )
// ACT: 0 none, 1 gelu, 2 relu.  TB: B given as [Ntot, K] (use B^T).
// STATS >= 0: emit per-block column sum/sumsq partials (y==1, Ntot==64).
// MERGEA: A tile = attention split-merge of this block's rows (K==64).
template <int ACT, bool TB, bool RES, int STATS, bool MERGEA>
__global__ void __launch_bounds__(256) k_gemm(const float* __restrict__ Aext, int aSel,
                                              const float* __restrict__ B,
                                              const float* __restrict__ bias,
                                              int resSel, int cSel, int Ntot, int K) {
    __shared__ float As[32 * 128];
    __shared__ float Bs[128 * 64];
    const float* A = (aSel >= 0) ? bufsel(aSel) : Aext;
    float* Cm = bufsel(cSel);
    const float* res = RES ? bufsel(resSel) : nullptr;

    int rb = blockIdx.x * 32;
    int n0 = blockIdx.y * 64;
    int tid = threadIdx.x;

    if (MERGEA) {
        // A tile = merged attention output for rows rb..rb+31 (K == 64)
        if (tid < 128) {
            int r = tid >> 2, h = tid & 3, q = rb + r;
            float mv[NSPLIT], mb = -1e30f;
#pragma unroll
            for (int sp = 0; sp < NSPLIT; sp++) {
                mv[sp] = g_mpart[(h * NSPLIT + sp) * NN + q];
                mb = fmaxf(mb, mv[sp]);
            }
            float L = 0.f, o[16] = {};
#pragma unroll
            for (int sp = 0; sp < NSPLIT; sp++) {
                float w = ex2f(mv[sp] - mb);
                int pidx = (h * NSPLIT + sp) * NN + q;
                L += g_lpart[pidx] * w;
                const float4* op4 = (const float4*)(g_opart + pidx * 16);
#pragma unroll
                for (int i = 0; i < 4; i++) {
                    float4 vv = op4[i];
                    o[4 * i + 0] = fmaf(vv.x, w, o[4 * i + 0]);
                    o[4 * i + 1] = fmaf(vv.y, w, o[4 * i + 1]);
                    o[4 * i + 2] = fmaf(vv.z, w, o[4 * i + 2]);
                    o[4 * i + 3] = fmaf(vv.w, w, o[4 * i + 3]);
                }
            }
            float inv = 1.0f / L;
#pragma unroll
            for (int d = 0; d < 16; d++) As[r * 64 + h * 16 + d] = o[d] * inv;
        }
    } else {
        for (int idx = tid; idx < 32 * K; idx += 256) As[idx] = A[rb * K + idx];
    }
    for (int idx = tid; idx < K * 64; idx += 256) {
        if (TB) {
            int n = idx / K;
            int k = idx - n * K;
            Bs[k * 64 + n] = B[(n0 + n) * K + k];
        } else {
            int k = idx >> 6;
            int n = idx & 63;
            Bs[k * 64 + n] = B[k * Ntot + n0 + n];
        }
    }
    __syncthreads();

    int tr = tid >> 4;       // 0..15 (rows tr, tr+16)
    int tc = tid & 15;       // 0..15 (cols tc*4..tc*4+3)
    float acc[2][4] = {};
    for (int k = 0; k < K; k++) {
        float a0 = As[tr * K + k];
        float a1 = As[(tr + 16) * K + k];
        float4 b = *(const float4*)&Bs[k * 64 + tc * 4];
        acc[0][0] = fmaf(a0, b.x, acc[0][0]);
        acc[0][1] = fmaf(a0, b.y, acc[0][1]);
        acc[0][2] = fmaf(a0, b.z, acc[0][2]);
        acc[0][3] = fmaf(a0, b.w, acc[0][3]);
        acc[1][0] = fmaf(a1, b.x, acc[1][0]);
        acc[1][1] = fmaf(a1, b.y, acc[1][1]);
        acc[1][2] = fmaf(a1, b.z, acc[1][2]);
        acc[1][3] = fmaf(a1, b.w, acc[1][3]);
    }
    float sl[4] = {}, ql[4] = {};
#pragma unroll
    for (int r = 0; r < 2; r++) {
        int row = rb + tr + r * 16;
#pragma unroll
        for (int i = 0; i < 4; i++) {
            int col = n0 + tc * 4 + i;
            float v = acc[r][i] + bias[col];
            if (RES) v += res[row * Ntot + col];
            if (ACT == 1) v = gelu_exact(v);
            if (ACT == 2) v = fmaxf(v, 0.0f);
            Cm[row * Ntot + col] = v;
            if (STATS >= 0) { sl[i] += v; ql[i] = fmaf(v, v, ql[i]); }
        }
    }
    if (STATS >= 0) {
        __syncthreads();   // done with As main-loop reads
#pragma unroll
        for (int i = 0; i < 4; i++) {
            As[tr * 128 + tc * 4 + i]      = sl[i];
            As[tr * 128 + 64 + tc * 4 + i] = ql[i];
        }
        __syncthreads();
        if (tid < 128) {
            float S = 0.f;
#pragma unroll
            for (int r = 0; r < 16; r++) S += As[r * 128 + tid];
            partsel(STATS)[blockIdx.x * 128 + tid] = S;
        }
    }
}

// ---------------- fused GAT+QKV GEMM: y in {xl, xr, Q, K, V} ---------------
// A = g_X [32x64 tile]. y0: xl=x@wl+bl; y1: xr=x@wr+br;
// y2..4: qkv = x@Wq^T+bq, col block (y-2)*64, written as Q fp32 / K,V bf16 split.
__global__ void __launch_bounds__(256) k_gemm5(const float* __restrict__ wl,
                                               const float* __restrict__ bl,
                                               const float* __restrict__ wr,
                                               const float* __restrict__ br,
                                               const float* __restrict__ wq,
                                               const float* __restrict__ bq) {
    __shared__ float As[32 * 64];
    __shared__ float Bs[64 * 64];
    int rb = blockIdx.x * 32;
    int y = blockIdx.y;
    int tid = threadIdx.x;
    int n0 = (y >= 2) ? (y - 2) * 64 : 0;

    for (int idx = tid; idx < 32 * 64; idx += 256) As[idx] = g_X[rb * 64 + idx];
    if (y == 0) {
        for (int idx = tid; idx < 64 * 64; idx += 256) Bs[idx] = wl[idx];
    } else if (y == 1) {
        for (int idx = tid; idx < 64 * 64; idx += 256) Bs[idx] = wr[idx];
    } else {
        for (int idx = tid; idx < 64 * 64; idx += 256) {
            int n = idx >> 6, k = idx & 63;
            Bs[k * 64 + n] = wq[(n0 + n) * 64 + k];
        }
    }
    __syncthreads();

    int tr = tid >> 4, tc = tid & 15;
    float acc[2][4] = {};
#pragma unroll
    for (int k = 0; k < 64; k++) {
        float a0 = As[tr * 64 + k];
        float a1 = As[(tr + 16) * 64 + k];
        float4 b = *(const float4*)&Bs[k * 64 + tc * 4];
        acc[0][0] = fmaf(a0, b.x, acc[0][0]);
        acc[0][1] = fmaf(a0, b.y, acc[0][1]);
        acc[0][2] = fmaf(a0, b.z, acc[0][2]);
        acc[0][3] = fmaf(a0, b.w, acc[0][3]);
        acc[1][0] = fmaf(a1, b.x, acc[1][0]);
        acc[1][1] = fmaf(a1, b.y, acc[1][1]);
        acc[1][2] = fmaf(a1, b.z, acc[1][2]);
        acc[1][3] = fmaf(a1, b.w, acc[1][3]);
    }
    const float* bias = (y == 0) ? bl : (y == 1) ? br : bq;
#pragma unroll
    for (int r = 0; r < 2; r++) {
        int row = rb + tr + r * 16;
#pragma unroll
        for (int i = 0; i < 4; i++) {
            int cl = tc * 4 + i;
            float v = acc[r][i] + bias[n0 + cl];
            if (y == 0) {
                g_XL[row * 64 + cl] = v;
            } else if (y == 1) {
                g_XR[row * 64 + cl] = v;
            } else {
                int which = y - 2, hh = cl >> 4, d = cl & 15;
                if (which == 0) {
                    g_Q[(hh * NN + row) * DHH + d] = v;
                } else {
                    unsigned hb = bfpack(0.f, v) & 0xffffu;
                    float hf = __uint_as_float(hb << 16);
                    unsigned lb = bfpack(0.f, v - hf) & 0xffffu;
                    if (which == 1) {
                        int o = (hh * NN + row) * KPAD + d;
                        g_K18h[o] = (unsigned short)hb;
                        g_K18l[o] = (unsigned short)lb;
                    } else {
                        int o = (hh * DHH + d) * NN + row;
                        g_Vth[o] = (unsigned short)hb;
                        g_Vtl[o] = (unsigned short)lb;
                    }
                }
            }
        }
    }
}

// ---------------- GATv2: fused one-pass, 4 edge-groups x 8 lanes -----------
__global__ void __launch_bounds__(256) k_gat(const float* __restrict__ att,
                                             const float* __restrict__ gbias) {
    const float L2E = 1.4426950408889634f;
    int warp = threadIdx.x >> 5, lane = threadIdx.x & 31;
    int grp = lane >> 3;
    unsigned gm = 0xFFu << (grp * 8);   // group-local shuffle mask
    int fb = (lane & 7) * 8;            // feature block [fb, fb+8)
    int v = blockIdx.x * 8 + warp;

    float4 xra = *(const float4*)&g_XR[v * 64 + fb];
    float4 xrb = *(const float4*)&g_XR[v * 64 + fb + 4];
    float4 ata = *(const float4*)&att[fb];
    float4 atb = *(const float4*)&att[fb + 4];
    ata.x *= L2E; ata.y *= L2E; ata.z *= L2E; ata.w *= L2E;
    atb.x *= L2E; atb.y *= L2E; atb.z *= L2E; atb.w *= L2E;

#define GAT_SCORE(E, XA, XB)                                                  \
    {                                                                         \
        float z, p = 0.f;                                                     \
        z = XA.x + xra.x; z = fmaxf(z, 0.2f * z); p = fmaf(z, ata.x, p);      \
        z = XA.y + xra.y; z = fmaxf(z, 0.2f * z); p = fmaf(z, ata.y, p);      \
        z = XA.z + xra.z; z = fmaxf(z, 0.2f * z); p = fmaf(z, ata.z, p);      \
        z = XA.w + xra.w; z = fmaxf(z, 0.2f * z); p = fmaf(z, ata.w, p);      \
        z = XB.x + xrb.x; z = fmaxf(z, 0.2f * z); p = fmaf(z, atb.x, p);      \
        z = XB.y + xrb.y; z = fmaxf(z, 0.2f * z); p = fmaf(z, atb.y, p);      \
        z = XB.z + xrb.z; z = fmaxf(z, 0.2f * z); p = fmaf(z, atb.z, p);      \
        z = XB.w + xrb.w; z = fmaxf(z, 0.2f * z); p = fmaf(z, atb.w, p);      \
        p += __shfl_xor_sync(gm, p, 1);                                       \
        p += __shfl_xor_sync(gm, p, 2);                                       \
        p += __shfl_xor_sync(gm, p, 4);                                       \
        E = p;                                                                \
    }

    // self-loop seeds group 0; other groups start empty (m=-inf, l=0, acc=0)
    float4 xa = *(const float4*)&g_XL[v * 64 + fb];
    float4 xb = *(const float4*)&g_XL[v * 64 + fb + 4];
    float e;
    GAT_SCORE(e, xa, xb);
    bool g0 = (grp == 0);
    float m = g0 ? e : -1e30f;
    float l = g0 ? 1.f : 0.f;
    float4 aca, acb;
    aca.x = g0 ? xa.x : 0.f; aca.y = g0 ? xa.y : 0.f;
    aca.z = g0 ? xa.z : 0.f; aca.w = g0 ? xa.w : 0.f;
    acb.x = g0 ? xb.x : 0.f; acb.y = g0 ? xb.y : 0.f;
    acb.z = g0 ? xb.z : 0.f; acb.w = g0 ? xb.w : 0.f;

    int beg = g_rowptr[v], end = g_rowptr[v + 1];
    int k = beg + grp;
    if (k < end) {
        int s = g_csrsrc[k];
        float4 nxa = *(const float4*)&g_XL[s * 64 + fb];
        float4 nxb = *(const float4*)&g_XL[s * 64 + fb + 4];
        while (true) {
            xa = nxa; xb = nxb;
            int kn = k + 4;
            if (kn < end) {      // group-uniform branch
                int sn = g_csrsrc[kn];
                nxa = *(const float4*)&g_XL[sn * 64 + fb];
                nxb = *(const float4*)&g_XL[sn * 64 + fb + 4];
            }
            GAT_SCORE(e, xa, xb);
            float nm = fmaxf(m, e);
            float sc = ex2f(m - nm);
            float w  = ex2f(e - nm);
            l = fmaf(l, sc, w);
            aca.x = fmaf(aca.x, sc, w * xa.x);
            aca.y = fmaf(aca.y, sc, w * xa.y);
            aca.z = fmaf(aca.z, sc, w * xa.z);
            aca.w = fmaf(aca.w, sc, w * xa.w);
            acb.x = fmaf(acb.x, sc, w * xb.x);
            acb.y = fmaf(acb.y, sc, w * xb.y);
            acb.z = fmaf(acb.z, sc, w * xb.z);
            acb.w = fmaf(acb.w, sc, w * xb.w);
            m = nm;
            k = kn;
            if (k >= end) break;
        }
    }
    __syncwarp();   // reconverge all 32 lanes before cross-group merge

    float mo = fmaxf(m, __shfl_xor_sync(0xffffffffu, m, 8));
    mo = fmaxf(mo, __shfl_xor_sync(0xffffffffu, mo, 16));
    float wq = ex2f(m - mo);
    l *= wq;
    l += __shfl_xor_sync(0xffffffffu, l, 8);
    l += __shfl_xor_sync(0xffffffffu, l, 16);
#define GAT_MRG(R)                                    \
    R *= wq;                                          \
    R += __shfl_xor_sync(0xffffffffu, R, 8);          \
    R += __shfl_xor_sync(0xffffffffu, R, 16);
    GAT_MRG(aca.x) GAT_MRG(aca.y) GAT_MRG(aca.z) GAT_MRG(aca.w)
    GAT_MRG(acb.x) GAT_MRG(acb.y) GAT_MRG(acb.z) GAT_MRG(acb.w)
    float inv = 1.0f / l;

    __shared__ float shs[512], shq[512];
    if (g0) {
        float4 bia = *(const float4*)&gbias[fb];
        float4 bib = *(const float4*)&gbias[fb + 4];
        float4 rxa = *(const float4*)&g_X[v * 64 + fb];
        float4 rxb = *(const float4*)&g_X[v * 64 + fb + 4];
        float4 oa, ob;
        oa.x = fmaf(aca.x, inv, bia.x + rxa.x);
        oa.y = fmaf(aca.y, inv, bia.y + rxa.y);
        oa.z = fmaf(aca.z, inv, bia.z + rxa.z);
        oa.w = fmaf(aca.w, inv, bia.w + rxa.w);
        ob.x = fmaf(acb.x, inv, bib.x + rxb.x);
        ob.y = fmaf(acb.y, inv, bib.y + rxb.y);
        ob.z = fmaf(acb.z, inv, bib.z + rxb.z);
        ob.w = fmaf(acb.w, inv, bib.w + rxb.w);
        *(float4*)&g_H1R[v * 64 + fb]     = oa;
        *(float4*)&g_H1R[v * 64 + fb + 4] = ob;
        float4 qa, qb;
        qa.x = oa.x * oa.x; qa.y = oa.y * oa.y; qa.z = oa.z * oa.z; qa.w = oa.w * oa.w;
        qb.x = ob.x * ob.x; qb.y = ob.y * ob.y; qb.z = ob.z * ob.z; qb.w = ob.w * ob.w;
        *(float4*)&shs[warp * 64 + fb]     = oa;
        *(float4*)&shs[warp * 64 + fb + 4] = ob;
        *(float4*)&shq[warp * 64 + fb]     = qa;
        *(float4*)&shq[warp * 64 + fb + 4] = qb;
    }
    __syncthreads();
    int t = threadIdx.x;
    if (t < 64) {
        float S = 0.f, Q = 0.f;
#pragma unroll
        for (int w = 0; w < 8; w++) { S += shs[w * 64 + t]; Q += shq[w * 64 + t]; }
        g_part1[blockIdx.x * 128 + t]      = S;
        g_part1[blockIdx.x * 128 + 64 + t] = Q;
    }
}

// ---------------- BatchNorm reduce (from per-block partials) ---------------
template <int NB>
__device__ void stats_reduceN(const float* part, float* mu, float* istd, float* scr) {
    int t = threadIdx.x;
    int f = t & 63, c = t >> 6;
    float s = 0.f, q = 0.f;
    for (int b = c; b < NB; b += 4) {
        s += part[b * 128 + f];
        q += part[b * 128 + 64 + f];
    }
    scr[t] = s; scr[256 + t] = q;
    __syncthreads();
    if (t < 64) {
        float S = scr[t] + scr[t + 64] + scr[t + 128] + scr[t + 192];
        float Q = scr[256 + t] + scr[256 + t + 64] + scr[256 + t + 128] + scr[256 + t + 192];
        float m = S * (1.0f / NN);
        mu[t] = m;
        istd[t] = rsqrtf(Q * (1.0f / NN) - m * m + 1e-5f);
    }
    __syncthreads();
}

// OUT0 = bn1(H1R) + bn2(H2R)
__global__ void __launch_bounds__(256) k_combine(const float* __restrict__ g1, const float* __restrict__ b1,
                                                 const float* __restrict__ g2, const float* __restrict__ b2) {
    __shared__ float scr[512];
    __shared__ float mu1[64], is1[64], mu2[64], is2[64];
    stats_reduceN<512>(g_part1, mu1, is1, scr);
    stats_reduceN<128>(g_part2, mu2, is2, scr);
    int t = threadIdx.x;
    int base = blockIdx.x * 4096;
#pragma unroll
    for (int i = 0; i < 16; i++) {
        int o = base + t + i * 256;
        int f = o & 63;
        float v1 = (g_H1R[o] - mu1[f]) * is1[f] * g1[f] + b1[f];
        float v2 = (g_H2R[o] - mu2[f]) * is2[f] * g2[f] + b2[f];
        g_OUT0[o] = v1 + v2;
    }
}

// X = relu(bn3(OUT))
__global__ void __launch_bounds__(256) k_bn3relu(const float* __restrict__ g3, const float* __restrict__ b3) {
    __shared__ float scr[512];
    __shared__ float mu[64], is[64];
    stats_reduceN<128>(g_part3, mu, is, scr);
    int t = threadIdx.x;
    int base = blockIdx.x * 4096;
#pragma unroll
    for (int i = 0; i < 16; i++) {
        int o = base + t + i * 256;
        int f = o & 63;
        float v = (g_OUT[o] - mu[f]) * is[f] * g3[f] + b3[f];
        g_X[o] = fmaxf(v, 0.0f);
    }
}

// ---------------- global attention (flash, bf16-split HMMA) -----------------
// grid (32 q-tiles of 128, 4 heads, NSPLIT key-splits), 256 threads (8 warps,
// 16 queries/warp). K/V pre-split to bf16 hi/lo in global; staging = uint4 copy.
__global__ void __launch_bounds__(256) k_attn() {
    __shared__ __align__(16) unsigned short sKh[256 * KPAD];
    __shared__ __align__(16) unsigned short sKl[256 * KPAD];
    __shared__ __align__(16) unsigned short sVh[16 * VPAD];
    __shared__ __align__(16) unsigned short sVl[16 * VPAD];

    int tid = threadIdx.x;
    int w = tid >> 5, lane = tid & 31;
    int gid = lane >> 2, t4 = lane & 3;
    int h = blockIdx.y, sp = blockIdx.z;
    int q0 = blockIdx.x * 128 + w * 16;
    const float cs = 0.25f * 1.4426950408889634f;   // (1/sqrt(dh)) * log2(e)

    // Q fragments (hi/lo bf16 split), scores in log2 domain
    unsigned qh[4], ql[4];
    {
        const float* r0p = g_Q + (h * NN + q0 + gid) * 16;
#pragma unroll
        for (int i = 0; i < 4; i++) {
            const float* rp = r0p + ((i & 1) ? 8 * 16 : 0);
            int d = ((i >> 1) ? 8 : 0) + t4 * 2;
            float x0 = rp[d] * cs, x1 = rp[d + 1] * cs;
            unsigned hh = bfpack(x1, x0);
            float h0 = __uint_as_float(hh << 16);
            float h1 = __uint_as_float(hh & 0xffff0000u);
            qh[i] = hh;
            ql[i] = bfpack(x1 - h1, x0 - h0);
        }
    }

    float o[8] = {};                     // O: [dim-half][c0..c3]
    float m0 = -1e30f, m1 = -1e30f, l0 = 0.f, l1 = 0.f;

    for (int ch = 0; ch < (NN / NSPLIT) / 256; ch++) {
        int base = sp * (NN / NSPLIT) + ch * 256;
        __syncthreads();
        // K staging: pure uint4 copy of pre-split padded rows
        {
            const uint4* s1 = (const uint4*)(g_K18h + (size_t)(h * NN + base) * KPAD);
            const uint4* s2 = (const uint4*)(g_K18l + (size_t)(h * NN + base) * KPAD);
            uint4* d1 = (uint4*)sKh;
            uint4* d2 = (uint4*)sKl;
            for (int i = tid; i < 576; i += 256) { d1[i] = s1[i]; d2[i] = s2[i]; }
            // V staging: pre-transposed rows, 32 uint4 per dim
            for (int i = tid; i < 512; i += 256) {
                int d = i >> 5, j = i & 31;
                ((uint4*)sVh)[d * 33 + j] =
                    ((const uint4*)(g_Vth + (size_t)(h * DHH + d) * NN + base))[j];
                ((uint4*)sVl)[d * 33 + j] =
                    ((const uint4*)(g_Vtl + (size_t)(h * DHH + d) * NN + base))[j];
            }
        }
        __syncthreads();

        for (int g = 0; g < 16; g++) {
            int kb = g * 16;
            float c[8] = {};             // two 16x8 S tiles
#pragma unroll
            for (int t = 0; t < 2; t++) {
                int krow = (kb + t * 8 + gid) * KPAD;
                unsigned b0h = *(const unsigned*)&sKh[krow + t4 * 2];
                unsigned b1h = *(const unsigned*)&sKh[krow + 8 + t4 * 2];
                unsigned b0l = *(const unsigned*)&sKl[krow + t4 * 2];
                unsigned b1l = *(const unsigned*)&sKl[krow + 8 + t4 * 2];
                float* ct = c + t * 4;
                mma16816(ct[0], ct[1], ct[2], ct[3], qh[0], qh[1], qh[2], qh[3], b0h, b1h);
                mma16816(ct[0], ct[1], ct[2], ct[3], qh[0], qh[1], qh[2], qh[3], b0l, b1l);
                mma16816(ct[0], ct[1], ct[2], ct[3], ql[0], ql[1], ql[2], ql[3], b0h, b1h);
            }
            // online softmax (log2 domain)
            float s0 = fmaxf(fmaxf(c[0], c[1]), fmaxf(c[4], c[5]));
            float s1 = fmaxf(fmaxf(c[2], c[3]), fmaxf(c[6], c[7]));
            s0 = fmaxf(s0, __shfl_xor_sync(0xffffffffu, s0, 1));
            s0 = fmaxf(s0, __shfl_xor_sync(0xffffffffu, s0, 2));
            s1 = fmaxf(s1, __shfl_xor_sync(0xffffffffu, s1, 1));
            s1 = fmaxf(s1, __shfl_xor_sync(0xffffffffu, s1, 2));
            float nm0 = fmaxf(m0, s0), nm1 = fmaxf(m1, s1);
            float sc0 = ex2f(m0 - nm0), sc1 = ex2f(m1 - nm1);
            m0 = nm0; m1 = nm1;
            l0 *= sc0; l1 *= sc1;
            o[0] *= sc0; o[1] *= sc0; o[2] *= sc1; o[3] *= sc1;
            o[4] *= sc0; o[5] *= sc0; o[6] *= sc1; o[7] *= sc1;
            float p0 = ex2f(c[0] - m0), p1 = ex2f(c[1] - m0);
            float p2 = ex2f(c[2] - m1), p3 = ex2f(c[3] - m1);
            float p4 = ex2f(c[4] - m0), p5 = ex2f(c[5] - m0);
            float p6 = ex2f(c[6] - m1), p7 = ex2f(c[7] - m1);
            l0 += (p0 + p1) + (p4 + p5);
            l1 += (p2 + p3) + (p6 + p7);
            unsigned a0 = bfpack(p1, p0);
            unsigned a1 = bfpack(p3, p2);
            unsigned a2 = bfpack(p5, p4);
            unsigned a3 = bfpack(p7, p6);
#pragma unroll
            for (int nh = 0; nh < 2; nh++) {
                int vrow = (nh * 8 + gid) * VPAD + kb;
                unsigned vb0h = *(const unsigned*)&sVh[vrow + t4 * 2];
                unsigned vb1h = *(const unsigned*)&sVh[vrow + 8 + t4 * 2];
                unsigned vb0l = *(const unsigned*)&sVl[vrow + t4 * 2];
                unsigned vb1l = *(const unsigned*)&sVl[vrow + 8 + t4 * 2];
                float* ot = o + nh * 4;
                mma16816(ot[0], ot[1], ot[2], ot[3], a0, a1, a2, a3, vb0h, vb1h);
                mma16816(ot[0], ot[1], ot[2], ot[3], a0, a1, a2, a3, vb0l, vb1l);
            }
        }
    }
    // finalize: quad-reduce l, write partials
    l0 += __shfl_xor_sync(0xffffffffu, l0, 1);
    l0 += __shfl_xor_sync(0xffffffffu, l0, 2);
    l1 += __shfl_xor_sync(0xffffffffu, l1, 1);
    l1 += __shfl_xor_sync(0xffffffffu, l1, 2);
    int r0 = q0 + gid, r1 = r0 + 8;
    int pidx0 = (h * NSPLIT + sp) * NN + r0;
    int pidx1 = (h * NSPLIT + sp) * NN + r1;
    float* op0 = g_opart + pidx0 * 16;
    float* op1 = g_opart + pidx1 * 16;
    op0[t4 * 2]         = o[0]; op0[t4 * 2 + 1]     = o[1];
    op0[8 + t4 * 2]     = o[4]; op0[8 + t4 * 2 + 1] = o[5];
    op1[t4 * 2]         = o[2]; op1[t4 * 2 + 1]     = o[3];
    op1[8 + t4 * 2]     = o[6]; op1[8 + t4 * 2 + 1] = o[7];
    if (t4 == 0) {
        g_mpart[pidx0] = m0; g_lpart[pidx0] = l0;
        g_mpart[pidx1] = m1; g_lpart[pidx1] = l1;
    }
}

// ---------------- pooling + classifier -------------------------------------
__global__ void k_bounds(const int* __restrict__ batch) {
    int t = threadIdx.x;
    if (t <= GG) {
        int lo = 0, hi = NN;
        while (lo < hi) {
            int mid = (lo + hi) >> 1;
            if (batch[mid] < t) lo = mid + 1; else hi = mid;
        }
        g_gbound[t] = lo;
    }
}

__global__ void __launch_bounds__(64) k_final(const float* __restrict__ fin_w,
                                              const float* __restrict__ fin_b,
                                              float* __restrict__ out) {
    int g = blockIdx.x, t = threadIdx.x;
    int s0 = g_gbound[g], s1 = g_gbound[g + 1];
    int cnt = s1 - s0;
    float s = 0.f;
    for (int r = s0; r < s1; r++) s += g_X[r * 64 + t];
    __shared__ float mean[64];
    __shared__ float lg[CC];
    __shared__ float lse;
    mean[t] = s / (float)max(cnt, 1);
    __syncthreads();
    if (t < CC) {
        float a = fin_b[t];
        for (int f = 0; f < 64; f++) a = fmaf(mean[f], fin_w[f * CC + t], a);
        lg[t] = a;
    }
    __syncthreads();
    if (t == 0) {
        float mx = lg[0];
        for (int c = 1; c < CC; c++) mx = fmaxf(mx, lg[c]);
        float se = 0.f;
        for (int c = 0; c < CC; c++) se += expf(lg[c] - mx);
        lse = mx + logf(se);
    }
    __syncthreads();
    if (t < CC) out[g * CC + t] = lg[t] - lse;
}

// ---------------- launch ----------------------------------------------------
extern "C" void kernel_launch(void* const* d_in, const int* in_sizes, int n_in,
                              void* d_out, int out_size) {
    const float* x         = (const float*)d_in[0];
    const int*   ei        = (const int*)d_in[1];
    const int*   batch     = (const int*)d_in[2];
    const float* pre_w1    = (const float*)d_in[3];
    const float* pre_b1    = (const float*)d_in[4];
    const float* pre_w2    = (const float*)d_in[5];
    const float* pre_b2    = (const float*)d_in[6];
    const float* gat_wl    = (const float*)d_in[7];
    const float* gat_bl    = (const float*)d_in[8];
    const float* gat_wr    = (const float*)d_in[9];
    const float* gat_br    = (const float*)d_in[10];
    const float* gat_att   = (const float*)d_in[11];
    const float* gat_bias  = (const float*)d_in[12];
    const float* attn_in_w = (const float*)d_in[13];
    const float* attn_in_b = (const float*)d_in[14];
    const float* attn_ow   = (const float*)d_in[15];
    const float* attn_ob   = (const float*)d_in[16];
    const float* bn1_g     = (const float*)d_in[17];
    const float* bn1_b     = (const float*)d_in[18];
    const float* bn2_g     = (const float*)d_in[19];
    const float* bn2_b     = (const float*)d_in[20];
    const float* bn3_g     = (const float*)d_in[21];
    const float* bn3_b     = (const float*)d_in[22];
    const float* mlp_w1    = (const float*)d_in[23];
    const float* mlp_b1    = (const float*)d_in[24];
    const float* mlp_w2    = (const float*)d_in[25];
    const float* mlp_b2    = (const float*)d_in[26];
    const float* fin_w     = (const float*)d_in[27];
    const float* fin_b     = (const float*)d_in[28];

    // CSR of incoming edges (same every layer)
    k_zero_cnt<<<16, 256>>>();
    k_hist<<<EE / 256, 256>>>(ei);
    k_scan<<<1, 1024>>>();
    k_scatter<<<EE / 256, 256>>>(ei);

    // preprocess MLP
    k_gemm<1, false, false, -1, false><<<dim3(128, 2), 256>>>(
        x, -1, pre_w1, pre_b1, -1, 1, 128, 9);
    k_gemm<1, false, false, -1, false><<<dim3(128, 1), 256>>>(
        nullptr, 1, pre_w2, pre_b2, -1, 0, 64, 128);

    for (int l = 0; l < LL; l++) {
        // fused GAT-transforms + QKV projection (xl, xr, Q, K-split, V-split)
        k_gemm5<<<dim3(128, 5), 256>>>(gat_wl + l * 64 * 64, gat_bl + l * 64,
                                       gat_wr + l * 64 * 64, gat_br + l * 64,
                                       attn_in_w + l * 192 * 64, attn_in_b + l * 192);
        k_gat<<<512, 256>>>(gat_att + l * 64, gat_bias + l * 64);

        // global attention (HMMA bf16-split flash)
        k_attn<<<dim3(32, 4, NSPLIT), 256>>>();
        // out proj with split-merge fused into A-load + residual + BN2 partials
        k_gemm<0, true, true, 2, true><<<dim3(128, 1), 256>>>(
            nullptr, -1, attn_ow + l * 64 * 64, attn_ob + l * 64, 0, 5, 64, 64);

        // combine (bn1 + bn2) + MLP + norm3
        k_combine<<<64, 256>>>(bn1_g + l * 64, bn1_b + l * 64, bn2_g + l * 64, bn2_b + l * 64);
        k_gemm<2, false, false, -1, false><<<dim3(128, 2), 256>>>(
            nullptr, 6, mlp_w1 + l * 64 * 128, mlp_b1 + l * 128, -1, 1, 128, 64);
        k_gemm<0, false, true, 3, false><<<dim3(128, 1), 256>>>(
            nullptr, 1, mlp_w2 + l * 128 * 64, mlp_b2 + l * 64, 6, 7, 64, 128);
        k_bn3relu<<<64, 256>>>(bn3_g + l * 64, bn3_b + l * 64);
    }

    // pooling + classifier
    k_bounds<<<1, 128>>>(batch);
    k_final<<<GG, 64>>>(fin_w, fin_b, (float*)d_out);
}